// round 8
// baseline (speedup 1.0000x reference)
#include <cuda_runtime.h>
#include <cuda_fp16.h>
#include <cstdint>
#include <cstddef>

// Problem sizes (fixed)
#define BATCH 4096
#define HDIM  1024
#define KDIM  1024
#define NDIM  4096

// ---------------------------------------------------------------------------
// Scratch (device globals -- allocation is forbidden)
// ---------------------------------------------------------------------------
__device__ __align__(1024) __half g_xh [BATCH * KDIM];
__device__ __align__(1024) __half g_hh [BATCH * KDIM];
__device__ __align__(1024) __half g_wih[NDIM  * KDIM];
__device__ __align__(1024) __half g_whh[NDIM  * KDIM];
__device__ __align__(16) __half g_pre_ih[(size_t)BATCH * NDIM];   // fp16 pre-activations
__device__ __align__(16) __half g_pre_hh[(size_t)BATCH * NDIM];

// ---------------------------------------------------------------------------
// fp32 -> fp16 preconversion.  Each thread: 16 floats (4 indep float4 loads).
// grid = (BATCH*KDIM/16/256, 4)
// ---------------------------------------------------------------------------
__global__ void __launch_bounds__(256) cvt_kernel(
    const float4* __restrict__ x, const float4* __restrict__ h,
    const float4* __restrict__ wih, const float4* __restrict__ whh)
{
    int i = blockIdx.x * blockDim.x + threadIdx.x;
    const float4* src; __half* dst;
    switch (blockIdx.y) {
        case 0:  src = x;   dst = g_xh;  break;
        case 1:  src = h;   dst = g_hh;  break;
        case 2:  src = wih; dst = g_wih; break;
        default: src = whh; dst = g_whh; break;
    }
    float4 v0 = src[4 * i];
    float4 v1 = src[4 * i + 1];
    float4 v2 = src[4 * i + 2];
    float4 v3 = src[4 * i + 3];
    __half2 o[8];
    o[0] = __floats2half2_rn(v0.x, v0.y);  o[1] = __floats2half2_rn(v0.z, v0.w);
    o[2] = __floats2half2_rn(v1.x, v1.y);  o[3] = __floats2half2_rn(v1.z, v1.w);
    o[4] = __floats2half2_rn(v2.x, v2.y);  o[5] = __floats2half2_rn(v2.z, v2.w);
    o[6] = __floats2half2_rn(v3.x, v3.y);  o[7] = __floats2half2_rn(v3.z, v3.w);
    uint4* d = (uint4*)(dst + 16 * (size_t)i);
    d[0] = ((uint4*)o)[0];
    d[1] = ((uint4*)o)[1];
}

// ---------------------------------------------------------------------------
// fp16 GEMM: C[M,N] = A[M,K] @ W[N,K]^T, fp32 accumulate, fp16 output.
// CTA tile 128x128x32(halves), warp tile 64x32, 5-stage cp.async (single sync),
// ldmatrix batched upfront + mma.m16n8k16 dense block.
// grid = (N/128, M/128, 2)  z: 0 = ih, 1 = hh.  block = 256 (8 warps, 2 CTA/SM)
// ---------------------------------------------------------------------------
#define BM 128
#define BN 128
#define BK 32                 // halves per k-tile (64 data bytes/row)
#define ROWB 80               // smem row stride in bytes (conflict-free LDSM)
#define STAGES 5
#define NK (KDIM / BK)        // 32
#define A_SM_BYTES (BM * ROWB)            // 10240
#define STAGE_BYTES (2 * A_SM_BYTES)      // 20480 (A then B)
#define SMEM_TOTAL (STAGES * STAGE_BYTES) // 102400 (x2 CTAs = 204800 <= 228KB)

__device__ __forceinline__ uint32_t smem_u32(const void* p) {
    uint32_t a;
    asm("{ .reg .u64 t; cvta.to.shared.u64 t, %1; cvt.u32.u64 %0, t; }" : "=r"(a) : "l"(p));
    return a;
}
__device__ __forceinline__ void cp16(uint32_t smem, const void* gmem) {
    asm volatile("cp.async.cg.shared.global [%0], [%1], 16;" :: "r"(smem), "l"(gmem));
}
#define LDSM_X4(r0, r1, r2, r3, addr) \
    asm volatile("ldmatrix.sync.aligned.m8n8.x4.shared.b16 {%0,%1,%2,%3}, [%4];" \
        : "=r"(r0), "=r"(r1), "=r"(r2), "=r"(r3) : "r"(addr))

__global__ void __launch_bounds__(256, 2) gemm_f16()
{
    extern __shared__ char smem[];
    const uint32_t sb = smem_u32(smem);
    const int tid  = threadIdx.x;
    const int lane = tid & 31;
    const int warp = tid >> 5;
    const int wm   = warp >> 2;   // 0..1 -> M 64-block
    const int wn   = warp & 3;    // 0..3 -> N 32-block

    const int z = blockIdx.z;
    const __half* __restrict__ A = z ? g_hh  : g_xh;
    const __half* __restrict__ W = z ? g_whh : g_wih;
    __half* __restrict__ C       = z ? g_pre_hh : g_pre_ih;
    const int bm = blockIdx.y * BM;
    const int bn = blockIdx.x * BN;

    float acc[4][4][4];
#pragma unroll
    for (int a = 0; a < 4; a++)
#pragma unroll
        for (int b = 0; b < 4; b++)
#pragma unroll
            for (int d = 0; d < 4; d++) acc[a][b][d] = 0.f;

    // loader: row = tid>>1 (0..127), chunk pair = (tid&1)*2 for A and B alike
    const int lrow = tid >> 1;
    const int lcp  = (tid & 1) * 2;
    const __half* gA0 = A + (size_t)(bm + lrow) * KDIM + lcp * 8;
    const __half* gW0 = W + (size_t)(bn + lrow) * KDIM + lcp * 8;
    const uint32_t sA0 = sb + lrow * ROWB + lcp * 16;
    const uint32_t sB0 = sA0 + A_SM_BYTES;

    auto issue = [&](int kt, int buf) {
        const size_t ko = (size_t)kt * BK;
        const uint32_t so = buf * STAGE_BYTES;
        cp16(sA0 + so,      gA0 + ko);
        cp16(sA0 + so + 16, gA0 + ko + 8);
        cp16(sB0 + so,      gW0 + ko);
        cp16(sB0 + so + 16, gW0 + ko + 8);
        asm volatile("cp.async.commit_group;");
    };

    issue(0, 0); issue(1, 1); issue(2, 2); issue(3, 3);

    // fragment base addresses (per thread)
    const int l15 = lane & 15, lhi = lane >> 4;
    const uint32_t aBase = sb + (wm * 64 + l15) * ROWB + lhi * 16;
    const uint32_t bBase = sb + A_SM_BYTES + (wn * 32 + l15) * ROWB + lhi * 16;

    int cbuf = 0, pbuf = 4;
    for (int kt = 0; kt < NK; kt++) {
        if (kt < NK - 3) {
            asm volatile("cp.async.wait_group 3;");
        } else if (kt == NK - 3) {
            asm volatile("cp.async.wait_group 2;");
        } else if (kt == NK - 2) {
            asm volatile("cp.async.wait_group 1;");
        } else {
            asm volatile("cp.async.wait_group 0;");
        }
        __syncthreads();
        if (kt + 4 < NK) {                 // writes buf (kt-1)%5: reads done pre-sync
            issue(kt + 4, pbuf);
            pbuf = (pbuf == STAGES - 1) ? 0 : pbuf + 1;
        }

        const uint32_t so = cbuf * STAGE_BYTES;
        cbuf = (cbuf == STAGES - 1) ? 0 : cbuf + 1;

        // ---- batch ALL fragment loads for both k16 slices ----
        uint32_t a[2][4][4];   // [ks][mt][reg]
        uint32_t b[2][4][2];   // [ks][nt][reg]
#pragma unroll
        for (int ks = 0; ks < 2; ks++) {
#pragma unroll
            for (int mt = 0; mt < 4; mt++)
                LDSM_X4(a[ks][mt][0], a[ks][mt][1], a[ks][mt][2], a[ks][mt][3],
                        aBase + so + mt * (16 * ROWB) + ks * 32);
            LDSM_X4(b[ks][0][0], b[ks][1][0], b[ks][0][1], b[ks][1][1],
                    bBase + so + ks * 32);
            LDSM_X4(b[ks][2][0], b[ks][3][0], b[ks][2][1], b[ks][3][1],
                    bBase + so + 16 * ROWB + ks * 32);
        }

        // ---- dense MMA block (32 HMMA) ----
#pragma unroll
        for (int ks = 0; ks < 2; ks++)
#pragma unroll
            for (int mt = 0; mt < 4; mt++)
#pragma unroll
                for (int nt = 0; nt < 4; nt++) {
                    asm volatile(
                        "mma.sync.aligned.m16n8k16.row.col.f32.f16.f16.f32 "
                        "{%0,%1,%2,%3}, {%4,%5,%6,%7}, {%8,%9}, {%0,%1,%2,%3};"
                        : "+f"(acc[mt][nt][0]), "+f"(acc[mt][nt][1]),
                          "+f"(acc[mt][nt][2]), "+f"(acc[mt][nt][3])
                        : "r"(a[ks][mt][0]), "r"(a[ks][mt][1]),
                          "r"(a[ks][mt][2]), "r"(a[ks][mt][3]),
                          "r"(b[ks][nt][0]), "r"(b[ks][nt][1]));
                }
    }

    // epilogue: fp32 acc -> fp16 store
#pragma unroll
    for (int mt = 0; mt < 4; mt++) {
#pragma unroll
        for (int nt = 0; nt < 4; nt++) {
            int gm = bm + wm * 64 + mt * 16 + (lane >> 2);
            int gn = bn + wn * 32 + nt * 8 + (lane & 3) * 2;
            *(__half2*)&C[(size_t)gm * NDIM + gn] =
                __floats2half2_rn(acc[mt][nt][0], acc[mt][nt][1]);
            *(__half2*)&C[(size_t)(gm + 8) * NDIM + gn] =
                __floats2half2_rn(acc[mt][nt][2], acc[mt][nt][3]);
        }
    }
}

// ---------------------------------------------------------------------------
// LayerNorm + LSTM cell epilogue.  One block per batch row, 256 threads.
// Reads fp16 pre-activations, computes in fp32.
// ---------------------------------------------------------------------------
__device__ __forceinline__ float sigmoidf_(float v) {
    return 1.0f / (1.0f + expf(-v));
}

__global__ void __launch_bounds__(256) ln_cell_kernel(
    const float* __restrict__ c_in,
    const float* __restrict__ b_ih,
    const float* __restrict__ gma,
    const float* __restrict__ bta,
    float* __restrict__ out)
{
    const int b   = blockIdx.x;
    const int tid = threadIdx.x;
    const int warp = tid >> 5, lane = tid & 31;

    __shared__ float s_ih[NDIM];
    __shared__ float s_hh[NDIM];
    __shared__ float stats[18];
    __shared__ float red[16];

    const uint4* pih = (const uint4*)(g_pre_ih + (size_t)b * NDIM);
    const uint4* phh = (const uint4*)(g_pre_hh + (size_t)b * NDIM);
    for (int i = tid; i < NDIM / 8; i += 256) {   // 512 uint4 per matrix row
        uint4 v = pih[i];
        const __half2* hp = (const __half2*)&v;
#pragma unroll
        for (int q = 0; q < 4; q++) {
            float2 f = __half22float2(hp[q]);
            s_ih[8 * i + 2 * q]     = f.x;
            s_ih[8 * i + 2 * q + 1] = f.y;
        }
        v = phh[i];
#pragma unroll
        for (int q = 0; q < 4; q++) {
            float2 f = __half22float2(hp[q]);
            s_hh[8 * i + 2 * q]     = f.x;
            s_hh[8 * i + 2 * q + 1] = f.y;
        }
    }
    __syncthreads();

    {
        const float* src = (warp & 1) ? s_hh : s_ih;
        const int gate = warp >> 1;
        float sum = 0.f, ss = 0.f;
        for (int j = lane; j < HDIM; j += 32) {
            float v = src[gate * HDIM + j];
            sum += v; ss += v * v;
        }
#pragma unroll
        for (int o = 16; o; o >>= 1) {
            sum += __shfl_xor_sync(0xffffffffu, sum, o);
            ss  += __shfl_xor_sync(0xffffffffu, ss,  o);
        }
        if (lane == 0) {
            float mu = sum * (1.0f / HDIM);
            stats[warp * 2]     = mu;
            stats[warp * 2 + 1] = ss * (1.0f / HDIM) - mu * mu;
        }
    }
    __syncthreads();

    float mu[8], rs[8];
#pragma unroll
    for (int t = 0; t < 8; t++) {
        mu[t] = stats[t * 2];
        rs[t] = rsqrtf(stats[t * 2 + 1] + 1e-5f);
    }

    float cvals[4], ovals[4];
    float csum = 0.f, css = 0.f;
#pragma unroll
    for (int ii = 0; ii < 4; ii++) {
        int j = tid + ii * 256;
        float gv[4];
#pragma unroll
        for (int g = 0; g < 4; g++) {
            int si = g * 2, sh = g * 2 + 1;
            float vih = s_ih[g * HDIM + j];
            float vhh = s_hh[g * HDIM + j];
            float li = gma[(2 * g) * HDIM + j] * (vih - mu[si]) * rs[si] + bta[(2 * g) * HDIM + j];
            float lh = gma[(2 * g + 1) * HDIM + j] * (vhh - mu[sh]) * rs[sh] + bta[(2 * g + 1) * HDIM + j];
            gv[g] = li + lh + b_ih[g * HDIM + j];
        }
        float ig = sigmoidf_(gv[0]);
        float fg = sigmoidf_(gv[1]);
        float ag = tanhf(gv[2]);
        float cn = fg * c_in[(size_t)b * HDIM + j] + ig * ag;
        cvals[ii] = cn;
        ovals[ii] = gv[3];
        csum += cn; css += cn * cn;
    }

#pragma unroll
    for (int o = 16; o; o >>= 1) {
        csum += __shfl_xor_sync(0xffffffffu, csum, o);
        css  += __shfl_xor_sync(0xffffffffu, css,  o);
    }
    if (lane == 0) { red[warp] = csum; red[8 + warp] = css; }
    __syncthreads();
    if (tid == 0) {
        float s = 0.f, q = 0.f;
#pragma unroll
        for (int k = 0; k < 8; k++) { s += red[k]; q += red[8 + k]; }
        float m = s * (1.0f / HDIM);
        stats[16] = m;
        stats[17] = q * (1.0f / HDIM) - m * m;
    }
    __syncthreads();

    const float cmu = stats[16];
    const float crs = rsqrtf(stats[17] + 1e-5f);
#pragma unroll
    for (int ii = 0; ii < 4; ii++) {
        int j = tid + ii * 256;
        float lnc = gma[8 * HDIM + j] * (cvals[ii] - cmu) * crs + bta[8 * HDIM + j];
        float hn = sigmoidf_(ovals[ii]) * tanhf(lnc);
        out[(size_t)b * HDIM + j] = hn;
        out[(size_t)BATCH * HDIM + (size_t)b * HDIM + j] = cvals[ii];
    }
}

// ---------------------------------------------------------------------------
// kernel_launch
// ---------------------------------------------------------------------------
extern "C" void kernel_launch(void* const* d_in, const int* in_sizes, int n_in,
                              void* d_out, int out_size)
{
    const float* x   = (const float*)d_in[0];
    const float* h   = (const float*)d_in[1];
    const float* c   = (const float*)d_in[2];
    const float* wih = (const float*)d_in[3];
    const float* whh = (const float*)d_in[4];
    const float* bih = (const float*)d_in[5];
    const float* gma = (const float*)d_in[6];
    const float* bta = (const float*)d_in[7];
    float* out = (float*)d_out;

    // 1) fp16 conversion of GEMM operands (16 elems/thread, MLP=4)
    dim3 cgrid(BATCH * KDIM / 16 / 256, 4);
    cvt_kernel<<<cgrid, 256>>>((const float4*)x, (const float4*)h,
                               (const float4*)wih, (const float4*)whh);

    // 2) both GEMMs in one launch (BK=32, 5-stage, single sync)
    cudaFuncSetAttribute(gemm_f16, cudaFuncAttributeMaxDynamicSharedMemorySize, SMEM_TOTAL);
    dim3 ggrid(NDIM / BN, BATCH / BM, 2);
    gemm_f16<<<ggrid, 256, SMEM_TOTAL>>>();

    // 3) layernorms + cell update (fp16 pre input)
    ln_cell_kernel<<<BATCH, 256>>>(c, bih, gma, bta, out);
}

// round 9
// speedup vs baseline: 1.1634x; 1.1634x over previous
#include <cuda_runtime.h>
#include <cuda_fp16.h>
#include <cstdint>
#include <cstddef>

// Problem sizes (fixed)
#define BATCH 4096
#define HDIM  1024
#define KDIM  1024
#define NDIM  4096

// ---------------------------------------------------------------------------
// Scratch (device globals -- allocation is forbidden)
// ---------------------------------------------------------------------------
__device__ __align__(1024) __half g_xh [BATCH * KDIM];
__device__ __align__(1024) __half g_hh [BATCH * KDIM];
__device__ __align__(1024) __half g_wih[NDIM  * KDIM];
__device__ __align__(1024) __half g_whh[NDIM  * KDIM];
__device__ __align__(16) __half g_pre_ih[(size_t)BATCH * NDIM];   // fp16 pre-activations
__device__ __align__(16) __half g_pre_hh[(size_t)BATCH * NDIM];

// ---------------------------------------------------------------------------
// fp32 -> fp16 preconversion.  Each thread: 16 floats (4 indep float4 loads).
// ---------------------------------------------------------------------------
__global__ void __launch_bounds__(256) cvt_kernel(
    const float4* __restrict__ x, const float4* __restrict__ h,
    const float4* __restrict__ wih, const float4* __restrict__ whh)
{
    int i = blockIdx.x * blockDim.x + threadIdx.x;
    const float4* src; __half* dst;
    switch (blockIdx.y) {
        case 0:  src = x;   dst = g_xh;  break;
        case 1:  src = h;   dst = g_hh;  break;
        case 2:  src = wih; dst = g_wih; break;
        default: src = whh; dst = g_whh; break;
    }
    float4 v0 = src[4 * i];
    float4 v1 = src[4 * i + 1];
    float4 v2 = src[4 * i + 2];
    float4 v3 = src[4 * i + 3];
    __half2 o[8];
    o[0] = __floats2half2_rn(v0.x, v0.y);  o[1] = __floats2half2_rn(v0.z, v0.w);
    o[2] = __floats2half2_rn(v1.x, v1.y);  o[3] = __floats2half2_rn(v1.z, v1.w);
    o[4] = __floats2half2_rn(v2.x, v2.y);  o[5] = __floats2half2_rn(v2.z, v2.w);
    o[6] = __floats2half2_rn(v3.x, v3.y);  o[7] = __floats2half2_rn(v3.z, v3.w);
    uint4* d = (uint4*)(dst + 16 * (size_t)i);
    d[0] = ((uint4*)o)[0];
    d[1] = ((uint4*)o)[1];
}

// ---------------------------------------------------------------------------
// fp16 GEMM: C = A @ W^T.  128x128x32 tile, 64x32 warp tile, 4-stage cp.async,
// single sync/window, cross-barrier LDSM preload (register pipelining).
// grid = (N/128, M/128, 2).  block = 256 (8 warps, 2 CTA/SM)
// ---------------------------------------------------------------------------
#define BM 128
#define BN 128
#define BK 32                 // halves per k-tile (64 data bytes/row)
#define ROWB 80               // smem row stride in bytes (conflict-free LDSM)
#define STAGES 4
#define NK (KDIM / BK)        // 32
#define A_SM_BYTES (BM * ROWB)            // 10240
#define STAGE_BYTES (2 * A_SM_BYTES)      // 20480 (A then B)
#define SMEM_TOTAL (STAGES * STAGE_BYTES) // 81920  (x2 CTAs = 163840)

__device__ __forceinline__ uint32_t smem_u32(const void* p) {
    uint32_t a;
    asm("{ .reg .u64 t; cvta.to.shared.u64 t, %1; cvt.u32.u64 %0, t; }" : "=r"(a) : "l"(p));
    return a;
}
__device__ __forceinline__ void cp16(uint32_t smem, const void* gmem) {
    asm volatile("cp.async.cg.shared.global [%0], [%1], 16;" :: "r"(smem), "l"(gmem));
}
#define LDSM_X4(r0, r1, r2, r3, addr) \
    asm volatile("ldmatrix.sync.aligned.m8n8.x4.shared.b16 {%0,%1,%2,%3}, [%4];" \
        : "=r"(r0), "=r"(r1), "=r"(r2), "=r"(r3) : "r"(addr))
#define MMA16816(acc, ar, br) \
    asm volatile( \
        "mma.sync.aligned.m16n8k16.row.col.f32.f16.f16.f32 " \
        "{%0,%1,%2,%3}, {%4,%5,%6,%7}, {%8,%9}, {%0,%1,%2,%3};" \
        : "+f"((acc)[0]), "+f"((acc)[1]), "+f"((acc)[2]), "+f"((acc)[3]) \
        : "r"((ar)[0]), "r"((ar)[1]), "r"((ar)[2]), "r"((ar)[3]), \
          "r"((br)[0]), "r"((br)[1]))

__global__ void __launch_bounds__(256, 2) gemm_f16()
{
    extern __shared__ char smem[];
    const uint32_t sb = smem_u32(smem);
    const int tid  = threadIdx.x;
    const int lane = tid & 31;
    const int warp = tid >> 5;
    const int wm   = warp >> 2;   // 0..1 -> M 64-block
    const int wn   = warp & 3;    // 0..3 -> N 32-block

    const int z = blockIdx.z;
    const __half* __restrict__ A = z ? g_hh  : g_xh;
    const __half* __restrict__ W = z ? g_whh : g_wih;
    __half* __restrict__ C       = z ? g_pre_hh : g_pre_ih;
    const int bm = blockIdx.y * BM;
    const int bn = blockIdx.x * BN;

    float acc[4][4][4];
#pragma unroll
    for (int a = 0; a < 4; a++)
#pragma unroll
        for (int b = 0; b < 4; b++)
#pragma unroll
            for (int d = 0; d < 4; d++) acc[a][b][d] = 0.f;

    // loader: row = tid>>1 (0..127), chunk pair = (tid&1)*2 for A and B alike
    const int lrow = tid >> 1;
    const int lcp  = (tid & 1) * 2;
    const __half* gA0 = A + (size_t)(bm + lrow) * KDIM + lcp * 8;
    const __half* gW0 = W + (size_t)(bn + lrow) * KDIM + lcp * 8;
    const uint32_t sA0 = sb + lrow * ROWB + lcp * 16;
    const uint32_t sB0 = sA0 + A_SM_BYTES;

    auto issue = [&](int kt) {
        const int buf = kt & (STAGES - 1);
        const size_t ko = (size_t)kt * BK;
        const uint32_t so = buf * STAGE_BYTES;
        cp16(sA0 + so,      gA0 + ko);
        cp16(sA0 + so + 16, gA0 + ko + 8);
        cp16(sB0 + so,      gW0 + ko);
        cp16(sB0 + so + 16, gW0 + ko + 8);
        asm volatile("cp.async.commit_group;");
    };

    issue(0); issue(1); issue(2);

    // fragment base addresses (per thread)
    const int l15 = lane & 15, lhi = lane >> 4;
    const uint32_t aBase = sb + (wm * 64 + l15) * ROWB + lhi * 16;
    const uint32_t bBase = sb + A_SM_BYTES + (wn * 32 + l15) * ROWB + lhi * 16;

    // prologue: tiles 0 and 1 arrived (2 groups allowed pending: tile 2)
    asm volatile("cp.async.wait_group 1;");
    __syncthreads();

    // preload ks0 fragments of tile 0
    uint32_t a0[4][4], b0[4][2];     // "current" ks0 fragments (preloaded)
#pragma unroll
    for (int mt = 0; mt < 4; mt++)
        LDSM_X4(a0[mt][0], a0[mt][1], a0[mt][2], a0[mt][3],
                aBase + mt * (16 * ROWB));
    LDSM_X4(b0[0][0], b0[1][0], b0[0][1], b0[1][1], bBase);
    LDSM_X4(b0[2][0], b0[3][0], b0[2][1], b0[3][1], bBase + 16 * ROWB);

    for (int kt = 0; kt < NK; kt++) {
        const uint32_t so  = (kt & (STAGES - 1)) * STAGE_BYTES;
        const uint32_t son = ((kt + 1) & (STAGES - 1)) * STAGE_BYTES;

        // ---- LDSM ks1 of tile kt ----
        uint32_t a1[4][4], b1[4][2];
#pragma unroll
        for (int mt = 0; mt < 4; mt++)
            LDSM_X4(a1[mt][0], a1[mt][1], a1[mt][2], a1[mt][3],
                    aBase + so + mt * (16 * ROWB) + 32);
        LDSM_X4(b1[0][0], b1[1][0], b1[0][1], b1[1][1], bBase + so + 32);
        LDSM_X4(b1[2][0], b1[3][0], b1[2][1], b1[3][1],
                bBase + so + 16 * ROWB + 32);

        // ---- MMA ks0 on preloaded fragments (hides ks1 LDSM latency) ----
#pragma unroll
        for (int mt = 0; mt < 4; mt++)
#pragma unroll
            for (int nt = 0; nt < 4; nt++)
                MMA16816(acc[mt][nt], a0[mt], b0[nt]);

        // ---- preload ks0 of tile kt+1 (arrival ensured by prev window) ----
        if (kt + 1 < NK) {
#pragma unroll
            for (int mt = 0; mt < 4; mt++)
                LDSM_X4(a0[mt][0], a0[mt][1], a0[mt][2], a0[mt][3],
                        aBase + son + mt * (16 * ROWB));
            LDSM_X4(b0[0][0], b0[1][0], b0[0][1], b0[1][1], bBase + son);
            LDSM_X4(b0[2][0], b0[3][0], b0[2][1], b0[3][1],
                    bBase + son + 16 * ROWB);
        }

        // ---- MMA ks1 ----
#pragma unroll
        for (int mt = 0; mt < 4; mt++)
#pragma unroll
            for (int nt = 0; nt < 4; nt++)
                MMA16816(acc[mt][nt], a1[mt], b1[nt]);

        // ---- pipeline bookkeeping: one sync per window ----
        if (kt + 3 < NK) {
            issue(kt + 3);                      // buf (kt-1)&3, reads done (prev sync)
            asm volatile("cp.async.wait_group 1;");   // tile kt+2 arrived
        } else {
            asm volatile("cp.async.wait_group 0;");
        }
        __syncthreads();
    }

    // epilogue: fp32 acc -> fp16 store
#pragma unroll
    for (int mt = 0; mt < 4; mt++) {
#pragma unroll
        for (int nt = 0; nt < 4; nt++) {
            int gm = bm + wm * 64 + mt * 16 + (lane >> 2);
            int gn = bn + wn * 32 + nt * 8 + (lane & 3) * 2;
            *(__half2*)&C[(size_t)gm * NDIM + gn] =
                __floats2half2_rn(acc[mt][nt][0], acc[mt][nt][1]);
            *(__half2*)&C[(size_t)(gm + 8) * NDIM + gn] =
                __floats2half2_rn(acc[mt][nt][2], acc[mt][nt][3]);
        }
    }
}

// ---------------------------------------------------------------------------
// LayerNorm + LSTM cell epilogue.  One block per batch row, 256 threads.
// ---------------------------------------------------------------------------
__device__ __forceinline__ float sigmoidf_(float v) {
    return 1.0f / (1.0f + expf(-v));
}

__global__ void __launch_bounds__(256) ln_cell_kernel(
    const float* __restrict__ c_in,
    const float* __restrict__ b_ih,
    const float* __restrict__ gma,
    const float* __restrict__ bta,
    float* __restrict__ out)
{
    const int b   = blockIdx.x;
    const int tid = threadIdx.x;
    const int warp = tid >> 5, lane = tid & 31;

    __shared__ float s_ih[NDIM];
    __shared__ float s_hh[NDIM];
    __shared__ float stats[18];
    __shared__ float red[16];

    const uint4* pih = (const uint4*)(g_pre_ih + (size_t)b * NDIM);
    const uint4* phh = (const uint4*)(g_pre_hh + (size_t)b * NDIM);
    for (int i = tid; i < NDIM / 8; i += 256) {
        uint4 v = pih[i];
        const __half2* hp = (const __half2*)&v;
#pragma unroll
        for (int q = 0; q < 4; q++) {
            float2 f = __half22float2(hp[q]);
            s_ih[8 * i + 2 * q]     = f.x;
            s_ih[8 * i + 2 * q + 1] = f.y;
        }
        v = phh[i];
#pragma unroll
        for (int q = 0; q < 4; q++) {
            float2 f = __half22float2(hp[q]);
            s_hh[8 * i + 2 * q]     = f.x;
            s_hh[8 * i + 2 * q + 1] = f.y;
        }
    }
    __syncthreads();

    {
        const float* src = (warp & 1) ? s_hh : s_ih;
        const int gate = warp >> 1;
        float sum = 0.f, ss = 0.f;
        for (int j = lane; j < HDIM; j += 32) {
            float v = src[gate * HDIM + j];
            sum += v; ss += v * v;
        }
#pragma unroll
        for (int o = 16; o; o >>= 1) {
            sum += __shfl_xor_sync(0xffffffffu, sum, o);
            ss  += __shfl_xor_sync(0xffffffffu, ss,  o);
        }
        if (lane == 0) {
            float mu = sum * (1.0f / HDIM);
            stats[warp * 2]     = mu;
            stats[warp * 2 + 1] = ss * (1.0f / HDIM) - mu * mu;
        }
    }
    __syncthreads();

    float mu[8], rs[8];
#pragma unroll
    for (int t = 0; t < 8; t++) {
        mu[t] = stats[t * 2];
        rs[t] = rsqrtf(stats[t * 2 + 1] + 1e-5f);
    }

    float cvals[4], ovals[4];
    float csum = 0.f, css = 0.f;
#pragma unroll
    for (int ii = 0; ii < 4; ii++) {
        int j = tid + ii * 256;
        float gv[4];
#pragma unroll
        for (int g = 0; g < 4; g++) {
            int si = g * 2, sh = g * 2 + 1;
            float vih = s_ih[g * HDIM + j];
            float vhh = s_hh[g * HDIM + j];
            float li = gma[(2 * g) * HDIM + j] * (vih - mu[si]) * rs[si] + bta[(2 * g) * HDIM + j];
            float lh = gma[(2 * g + 1) * HDIM + j] * (vhh - mu[sh]) * rs[sh] + bta[(2 * g + 1) * HDIM + j];
            gv[g] = li + lh + b_ih[g * HDIM + j];
        }
        float ig = sigmoidf_(gv[0]);
        float fg = sigmoidf_(gv[1]);
        float ag = tanhf(gv[2]);
        float cn = fg * c_in[(size_t)b * HDIM + j] + ig * ag;
        cvals[ii] = cn;
        ovals[ii] = gv[3];
        csum += cn; css += cn * cn;
    }

#pragma unroll
    for (int o = 16; o; o >>= 1) {
        csum += __shfl_xor_sync(0xffffffffu, csum, o);
        css  += __shfl_xor_sync(0xffffffffu, css,  o);
    }
    if (lane == 0) { red[warp] = csum; red[8 + warp] = css; }
    __syncthreads();
    if (tid == 0) {
        float s = 0.f, q = 0.f;
#pragma unroll
        for (int k = 0; k < 8; k++) { s += red[k]; q += red[8 + k]; }
        float m = s * (1.0f / HDIM);
        stats[16] = m;
        stats[17] = q * (1.0f / HDIM) - m * m;
    }
    __syncthreads();

    const float cmu = stats[16];
    const float crs = rsqrtf(stats[17] + 1e-5f);
#pragma unroll
    for (int ii = 0; ii < 4; ii++) {
        int j = tid + ii * 256;
        float lnc = gma[8 * HDIM + j] * (cvals[ii] - cmu) * crs + bta[8 * HDIM + j];
        float hn = sigmoidf_(ovals[ii]) * tanhf(lnc);
        out[(size_t)b * HDIM + j] = hn;
        out[(size_t)BATCH * HDIM + (size_t)b * HDIM + j] = cvals[ii];
    }
}

// ---------------------------------------------------------------------------
// kernel_launch
// ---------------------------------------------------------------------------
extern "C" void kernel_launch(void* const* d_in, const int* in_sizes, int n_in,
                              void* d_out, int out_size)
{
    const float* x   = (const float*)d_in[0];
    const float* h   = (const float*)d_in[1];
    const float* c   = (const float*)d_in[2];
    const float* wih = (const float*)d_in[3];
    const float* whh = (const float*)d_in[4];
    const float* bih = (const float*)d_in[5];
    const float* gma = (const float*)d_in[6];
    const float* bta = (const float*)d_in[7];
    float* out = (float*)d_out;

    // 1) fp16 conversion of GEMM operands
    dim3 cgrid(BATCH * KDIM / 16 / 256, 4);
    cvt_kernel<<<cgrid, 256>>>((const float4*)x, (const float4*)h,
                               (const float4*)wih, (const float4*)whh);

    // 2) both GEMMs in one launch (BK=32, 4-stage, cross-barrier LDSM preload)
    cudaFuncSetAttribute(gemm_f16, cudaFuncAttributeMaxDynamicSharedMemorySize, SMEM_TOTAL);
    dim3 ggrid(NDIM / BN, BATCH / BM, 2);
    gemm_f16<<<ggrid, 256, SMEM_TOTAL>>>();

    // 3) layernorms + cell update (fp16 pre input)
    ln_cell_kernel<<<BATCH, 256>>>(c, bih, gma, bta, out);
}

// round 10
// speedup vs baseline: 1.2112x; 1.0411x over previous
#include <cuda_runtime.h>
#include <cuda_fp16.h>
#include <cstdint>
#include <cstddef>

// Problem sizes (fixed)
#define BATCH 4096
#define HDIM  1024
#define KDIM  1024
#define NDIM  4096

// ---------------------------------------------------------------------------
// Scratch (device globals -- allocation is forbidden)
// ---------------------------------------------------------------------------
__device__ __align__(1024) __half g_xh [BATCH * KDIM];
__device__ __align__(1024) __half g_hh [BATCH * KDIM];
__device__ __align__(1024) __half g_wih[NDIM  * KDIM];
__device__ __align__(1024) __half g_whh[NDIM  * KDIM];
__device__ __align__(16) __half g_pre_ih[(size_t)BATCH * NDIM];   // fp16 pre-activations
__device__ __align__(16) __half g_pre_hh[(size_t)BATCH * NDIM];

// ---------------------------------------------------------------------------
// fp32 -> fp16 preconversion.  Each thread: 16 floats (4 indep float4 loads).
// ---------------------------------------------------------------------------
__global__ void __launch_bounds__(256) cvt_kernel(
    const float4* __restrict__ x, const float4* __restrict__ h,
    const float4* __restrict__ wih, const float4* __restrict__ whh)
{
    int i = blockIdx.x * blockDim.x + threadIdx.x;
    const float4* src; __half* dst;
    switch (blockIdx.y) {
        case 0:  src = x;   dst = g_xh;  break;
        case 1:  src = h;   dst = g_hh;  break;
        case 2:  src = wih; dst = g_wih; break;
        default: src = whh; dst = g_whh; break;
    }
    float4 v0 = src[4 * i];
    float4 v1 = src[4 * i + 1];
    float4 v2 = src[4 * i + 2];
    float4 v3 = src[4 * i + 3];
    __half2 o[8];
    o[0] = __floats2half2_rn(v0.x, v0.y);  o[1] = __floats2half2_rn(v0.z, v0.w);
    o[2] = __floats2half2_rn(v1.x, v1.y);  o[3] = __floats2half2_rn(v1.z, v1.w);
    o[4] = __floats2half2_rn(v2.x, v2.y);  o[5] = __floats2half2_rn(v2.z, v2.w);
    o[6] = __floats2half2_rn(v3.x, v3.y);  o[7] = __floats2half2_rn(v3.z, v3.w);
    uint4* d = (uint4*)(dst + 16 * (size_t)i);
    d[0] = ((uint4*)o)[0];
    d[1] = ((uint4*)o)[1];
}

// ---------------------------------------------------------------------------
// fp16 GEMM: C = A @ W^T.  128x128x32 tile, 64x32 warp tile, 4-stage cp.async,
// single sync/window, cross-barrier LDSM preload.   (R9 schedule, FROZEN)
// ---------------------------------------------------------------------------
#define BM 128
#define BN 128
#define BK 32
#define ROWB 80
#define STAGES 4
#define NK (KDIM / BK)
#define A_SM_BYTES (BM * ROWB)
#define STAGE_BYTES (2 * A_SM_BYTES)
#define SMEM_TOTAL (STAGES * STAGE_BYTES)

__device__ __forceinline__ uint32_t smem_u32(const void* p) {
    uint32_t a;
    asm("{ .reg .u64 t; cvta.to.shared.u64 t, %1; cvt.u32.u64 %0, t; }" : "=r"(a) : "l"(p));
    return a;
}
__device__ __forceinline__ void cp16(uint32_t smem, const void* gmem) {
    asm volatile("cp.async.cg.shared.global [%0], [%1], 16;" :: "r"(smem), "l"(gmem));
}
#define LDSM_X4(r0, r1, r2, r3, addr) \
    asm volatile("ldmatrix.sync.aligned.m8n8.x4.shared.b16 {%0,%1,%2,%3}, [%4];" \
        : "=r"(r0), "=r"(r1), "=r"(r2), "=r"(r3) : "r"(addr))
#define MMA16816(acc, ar, br) \
    asm volatile( \
        "mma.sync.aligned.m16n8k16.row.col.f32.f16.f16.f32 " \
        "{%0,%1,%2,%3}, {%4,%5,%6,%7}, {%8,%9}, {%0,%1,%2,%3};" \
        : "+f"((acc)[0]), "+f"((acc)[1]), "+f"((acc)[2]), "+f"((acc)[3]) \
        : "r"((ar)[0]), "r"((ar)[1]), "r"((ar)[2]), "r"((ar)[3]), \
          "r"((br)[0]), "r"((br)[1]))

__global__ void __launch_bounds__(256, 2) gemm_f16()
{
    extern __shared__ char smem[];
    const uint32_t sb = smem_u32(smem);
    const int tid  = threadIdx.x;
    const int lane = tid & 31;
    const int warp = tid >> 5;
    const int wm   = warp >> 2;
    const int wn   = warp & 3;

    const int z = blockIdx.z;
    const __half* __restrict__ A = z ? g_hh  : g_xh;
    const __half* __restrict__ W = z ? g_whh : g_wih;
    __half* __restrict__ C       = z ? g_pre_hh : g_pre_ih;
    const int bm = blockIdx.y * BM;
    const int bn = blockIdx.x * BN;

    float acc[4][4][4];
#pragma unroll
    for (int a = 0; a < 4; a++)
#pragma unroll
        for (int b = 0; b < 4; b++)
#pragma unroll
            for (int d = 0; d < 4; d++) acc[a][b][d] = 0.f;

    const int lrow = tid >> 1;
    const int lcp  = (tid & 1) * 2;
    const __half* gA0 = A + (size_t)(bm + lrow) * KDIM + lcp * 8;
    const __half* gW0 = W + (size_t)(bn + lrow) * KDIM + lcp * 8;
    const uint32_t sA0 = sb + lrow * ROWB + lcp * 16;
    const uint32_t sB0 = sA0 + A_SM_BYTES;

    auto issue = [&](int kt) {
        const int buf = kt & (STAGES - 1);
        const size_t ko = (size_t)kt * BK;
        const uint32_t so = buf * STAGE_BYTES;
        cp16(sA0 + so,      gA0 + ko);
        cp16(sA0 + so + 16, gA0 + ko + 8);
        cp16(sB0 + so,      gW0 + ko);
        cp16(sB0 + so + 16, gW0 + ko + 8);
        asm volatile("cp.async.commit_group;");
    };

    issue(0); issue(1); issue(2);

    const int l15 = lane & 15, lhi = lane >> 4;
    const uint32_t aBase = sb + (wm * 64 + l15) * ROWB + lhi * 16;
    const uint32_t bBase = sb + A_SM_BYTES + (wn * 32 + l15) * ROWB + lhi * 16;

    asm volatile("cp.async.wait_group 1;");
    __syncthreads();

    uint32_t a0[4][4], b0[4][2];
#pragma unroll
    for (int mt = 0; mt < 4; mt++)
        LDSM_X4(a0[mt][0], a0[mt][1], a0[mt][2], a0[mt][3],
                aBase + mt * (16 * ROWB));
    LDSM_X4(b0[0][0], b0[1][0], b0[0][1], b0[1][1], bBase);
    LDSM_X4(b0[2][0], b0[3][0], b0[2][1], b0[3][1], bBase + 16 * ROWB);

    for (int kt = 0; kt < NK; kt++) {
        const uint32_t so  = (kt & (STAGES - 1)) * STAGE_BYTES;
        const uint32_t son = ((kt + 1) & (STAGES - 1)) * STAGE_BYTES;

        uint32_t a1[4][4], b1[4][2];
#pragma unroll
        for (int mt = 0; mt < 4; mt++)
            LDSM_X4(a1[mt][0], a1[mt][1], a1[mt][2], a1[mt][3],
                    aBase + so + mt * (16 * ROWB) + 32);
        LDSM_X4(b1[0][0], b1[1][0], b1[0][1], b1[1][1], bBase + so + 32);
        LDSM_X4(b1[2][0], b1[3][0], b1[2][1], b1[3][1],
                bBase + so + 16 * ROWB + 32);

#pragma unroll
        for (int mt = 0; mt < 4; mt++)
#pragma unroll
            for (int nt = 0; nt < 4; nt++)
                MMA16816(acc[mt][nt], a0[mt], b0[nt]);

        if (kt + 1 < NK) {
#pragma unroll
            for (int mt = 0; mt < 4; mt++)
                LDSM_X4(a0[mt][0], a0[mt][1], a0[mt][2], a0[mt][3],
                        aBase + son + mt * (16 * ROWB));
            LDSM_X4(b0[0][0], b0[1][0], b0[0][1], b0[1][1], bBase + son);
            LDSM_X4(b0[2][0], b0[3][0], b0[2][1], b0[3][1],
                    bBase + son + 16 * ROWB);
        }

#pragma unroll
        for (int mt = 0; mt < 4; mt++)
#pragma unroll
            for (int nt = 0; nt < 4; nt++)
                MMA16816(acc[mt][nt], a1[mt], b1[nt]);

        if (kt + 3 < NK) {
            issue(kt + 3);
            asm volatile("cp.async.wait_group 1;");
        } else {
            asm volatile("cp.async.wait_group 0;");
        }
        __syncthreads();
    }

#pragma unroll
    for (int mt = 0; mt < 4; mt++) {
#pragma unroll
        for (int nt = 0; nt < 4; nt++) {
            int gm = bm + wm * 64 + mt * 16 + (lane >> 2);
            int gn = bn + wn * 32 + nt * 8 + (lane & 3) * 2;
            *(__half2*)&C[(size_t)gm * NDIM + gn] =
                __floats2half2_rn(acc[mt][nt][0], acc[mt][nt][1]);
            *(__half2*)&C[(size_t)(gm + 8) * NDIM + gn] =
                __floats2half2_rn(acc[mt][nt][2], acc[mt][nt][3]);
        }
    }
}

// ---------------------------------------------------------------------------
// LayerNorm + LSTM cell epilogue.  One block per batch row, 256 threads.
// i/f/a gates use MUFU.TANH approx (error damped through c_new LN);
// o-gate and final tanh stay on the accurate path.
// ---------------------------------------------------------------------------
__device__ __forceinline__ float sigmoidf_(float v) {
    return 1.0f / (1.0f + expf(-v));
}
__device__ __forceinline__ float tanh_ap(float x) {
    float y;
    asm("tanh.approx.f32 %0, %1;" : "=f"(y) : "f"(x));
    return y;
}
__device__ __forceinline__ float sigmoid_ap(float x) {   // 1 MUFU
    return fmaf(tanh_ap(0.5f * x), 0.5f, 0.5f);
}

__global__ void __launch_bounds__(256) ln_cell_kernel(
    const float* __restrict__ c_in,
    const float* __restrict__ b_ih,
    const float* __restrict__ gma,
    const float* __restrict__ bta,
    float* __restrict__ out)
{
    const int b   = blockIdx.x;
    const int tid = threadIdx.x;
    const int warp = tid >> 5, lane = tid & 31;

    __shared__ float s_ih[NDIM];
    __shared__ float s_hh[NDIM];
    __shared__ float stats[18];
    __shared__ float red[16];

    const uint4* pih = (const uint4*)(g_pre_ih + (size_t)b * NDIM);
    const uint4* phh = (const uint4*)(g_pre_hh + (size_t)b * NDIM);
    for (int i = tid; i < NDIM / 8; i += 256) {
        uint4 v = pih[i];
        const __half2* hp = (const __half2*)&v;
#pragma unroll
        for (int q = 0; q < 4; q++) {
            float2 f = __half22float2(hp[q]);
            s_ih[8 * i + 2 * q]     = f.x;
            s_ih[8 * i + 2 * q + 1] = f.y;
        }
        v = phh[i];
#pragma unroll
        for (int q = 0; q < 4; q++) {
            float2 f = __half22float2(hp[q]);
            s_hh[8 * i + 2 * q]     = f.x;
            s_hh[8 * i + 2 * q + 1] = f.y;
        }
    }
    __syncthreads();

    {
        const float* src = (warp & 1) ? s_hh : s_ih;
        const int gate = warp >> 1;
        float sum = 0.f, ss = 0.f;
        for (int j = lane; j < HDIM; j += 32) {
            float v = src[gate * HDIM + j];
            sum += v; ss += v * v;
        }
#pragma unroll
        for (int o = 16; o; o >>= 1) {
            sum += __shfl_xor_sync(0xffffffffu, sum, o);
            ss  += __shfl_xor_sync(0xffffffffu, ss,  o);
        }
        if (lane == 0) {
            float mu = sum * (1.0f / HDIM);
            stats[warp * 2]     = mu;
            stats[warp * 2 + 1] = ss * (1.0f / HDIM) - mu * mu;
        }
    }
    __syncthreads();

    float mu[8], rs[8];
#pragma unroll
    for (int t = 0; t < 8; t++) {
        mu[t] = stats[t * 2];
        rs[t] = rsqrtf(stats[t * 2 + 1] + 1e-5f);
    }

    float cvals[4], ovals[4];
    float csum = 0.f, css = 0.f;
#pragma unroll
    for (int ii = 0; ii < 4; ii++) {
        int j = tid + ii * 256;
        float gv[4];
#pragma unroll
        for (int g = 0; g < 4; g++) {
            int si = g * 2, sh = g * 2 + 1;
            float vih = s_ih[g * HDIM + j];
            float vhh = s_hh[g * HDIM + j];
            float li = gma[(2 * g) * HDIM + j] * (vih - mu[si]) * rs[si] + bta[(2 * g) * HDIM + j];
            float lh = gma[(2 * g + 1) * HDIM + j] * (vhh - mu[sh]) * rs[sh] + bta[(2 * g + 1) * HDIM + j];
            gv[g] = li + lh + b_ih[g * HDIM + j];
        }
        float ig = sigmoid_ap(gv[0]);          // approx (damped by LN on c_new)
        float fg = sigmoid_ap(gv[1]);          // approx
        float ag = tanh_ap(gv[2]);             // approx
        float cn = fg * c_in[(size_t)b * HDIM + j] + ig * ag;
        cvals[ii] = cn;
        ovals[ii] = gv[3];
        csum += cn; css += cn * cn;
    }

#pragma unroll
    for (int o = 16; o; o >>= 1) {
        csum += __shfl_xor_sync(0xffffffffu, csum, o);
        css  += __shfl_xor_sync(0xffffffffu, css,  o);
    }
    if (lane == 0) { red[warp] = csum; red[8 + warp] = css; }
    __syncthreads();
    if (tid == 0) {
        float s = 0.f, q = 0.f;
#pragma unroll
        for (int k = 0; k < 8; k++) { s += red[k]; q += red[8 + k]; }
        float m = s * (1.0f / HDIM);
        stats[16] = m;
        stats[17] = q * (1.0f / HDIM) - m * m;
    }
    __syncthreads();

    const float cmu = stats[16];
    const float crs = rsqrtf(stats[17] + 1e-5f);
#pragma unroll
    for (int ii = 0; ii < 4; ii++) {
        int j = tid + ii * 256;
        float lnc = gma[8 * HDIM + j] * (cvals[ii] - cmu) * crs + bta[8 * HDIM + j];
        float hn = sigmoidf_(ovals[ii]) * tanhf(lnc);   // accurate path to h_new
        out[(size_t)b * HDIM + j] = hn;
        out[(size_t)BATCH * HDIM + (size_t)b * HDIM + j] = cvals[ii];
    }
}

// ---------------------------------------------------------------------------
// kernel_launch
// ---------------------------------------------------------------------------
extern "C" void kernel_launch(void* const* d_in, const int* in_sizes, int n_in,
                              void* d_out, int out_size)
{
    const float* x   = (const float*)d_in[0];
    const float* h   = (const float*)d_in[1];
    const float* c   = (const float*)d_in[2];
    const float* wih = (const float*)d_in[3];
    const float* whh = (const float*)d_in[4];
    const float* bih = (const float*)d_in[5];
    const float* gma = (const float*)d_in[6];
    const float* bta = (const float*)d_in[7];
    float* out = (float*)d_out;

    dim3 cgrid(BATCH * KDIM / 16 / 256, 4);
    cvt_kernel<<<cgrid, 256>>>((const float4*)x, (const float4*)h,
                               (const float4*)wih, (const float4*)whh);

    cudaFuncSetAttribute(gemm_f16, cudaFuncAttributeMaxDynamicSharedMemorySize, SMEM_TOTAL);
    dim3 ggrid(NDIM / BN, BATCH / BM, 2);
    gemm_f16<<<ggrid, 256, SMEM_TOTAL>>>();

    ln_cell_kernel<<<BATCH, 256>>>(c, bih, gma, bta, out);
}

// round 11
// speedup vs baseline: 1.2183x; 1.0059x over previous
#include <cuda_runtime.h>
#include <cuda_fp16.h>
#include <cstdint>
#include <cstddef>

// Problem sizes (fixed)
#define BATCH 4096
#define HDIM  1024
#define KDIM  1024
#define NDIM  4096

// ---------------------------------------------------------------------------
// Scratch (device globals -- allocation is forbidden)
// ---------------------------------------------------------------------------
__device__ __align__(1024) __half g_xh [BATCH * KDIM];
__device__ __align__(1024) __half g_hh [BATCH * KDIM];
__device__ __align__(1024) __half g_wih[NDIM  * KDIM];
__device__ __align__(1024) __half g_whh[NDIM  * KDIM];
__device__ __align__(16) __half g_pre_ih[(size_t)BATCH * NDIM];   // fp16 pre-activations
__device__ __align__(16) __half g_pre_hh[(size_t)BATCH * NDIM];

// ---------------------------------------------------------------------------
// fp32 -> fp16 preconversion.  Each thread: 16 floats (4 indep float4 loads).
// ---------------------------------------------------------------------------
__global__ void __launch_bounds__(256) cvt_kernel(
    const float4* __restrict__ x, const float4* __restrict__ h,
    const float4* __restrict__ wih, const float4* __restrict__ whh)
{
    int i = blockIdx.x * blockDim.x + threadIdx.x;
    const float4* src; __half* dst;
    switch (blockIdx.y) {
        case 0:  src = x;   dst = g_xh;  break;
        case 1:  src = h;   dst = g_hh;  break;
        case 2:  src = wih; dst = g_wih; break;
        default: src = whh; dst = g_whh; break;
    }
    float4 v0 = src[4 * i];
    float4 v1 = src[4 * i + 1];
    float4 v2 = src[4 * i + 2];
    float4 v3 = src[4 * i + 3];
    __half2 o[8];
    o[0] = __floats2half2_rn(v0.x, v0.y);  o[1] = __floats2half2_rn(v0.z, v0.w);
    o[2] = __floats2half2_rn(v1.x, v1.y);  o[3] = __floats2half2_rn(v1.z, v1.w);
    o[4] = __floats2half2_rn(v2.x, v2.y);  o[5] = __floats2half2_rn(v2.z, v2.w);
    o[6] = __floats2half2_rn(v3.x, v3.y);  o[7] = __floats2half2_rn(v3.z, v3.w);
    uint4* d = (uint4*)(dst + 16 * (size_t)i);
    d[0] = ((uint4*)o)[0];
    d[1] = ((uint4*)o)[1];
}

// ---------------------------------------------------------------------------
// fp16 GEMM: C = A @ W^T.  128x128x32 tile, 64x32 warp tile, 4-stage cp.async,
// single sync/window, cross-barrier LDSM preload.   (R9 schedule, FROZEN)
// ---------------------------------------------------------------------------
#define BM 128
#define BN 128
#define BK 32
#define ROWB 80
#define STAGES 4
#define NK (KDIM / BK)
#define A_SM_BYTES (BM * ROWB)
#define STAGE_BYTES (2 * A_SM_BYTES)
#define SMEM_TOTAL (STAGES * STAGE_BYTES)

__device__ __forceinline__ uint32_t smem_u32(const void* p) {
    uint32_t a;
    asm("{ .reg .u64 t; cvta.to.shared.u64 t, %1; cvt.u32.u64 %0, t; }" : "=r"(a) : "l"(p));
    return a;
}
__device__ __forceinline__ void cp16(uint32_t smem, const void* gmem) {
    asm volatile("cp.async.cg.shared.global [%0], [%1], 16;" :: "r"(smem), "l"(gmem));
}
#define LDSM_X4(r0, r1, r2, r3, addr) \
    asm volatile("ldmatrix.sync.aligned.m8n8.x4.shared.b16 {%0,%1,%2,%3}, [%4];" \
        : "=r"(r0), "=r"(r1), "=r"(r2), "=r"(r3) : "r"(addr))
#define MMA16816(acc, ar, br) \
    asm volatile( \
        "mma.sync.aligned.m16n8k16.row.col.f32.f16.f16.f32 " \
        "{%0,%1,%2,%3}, {%4,%5,%6,%7}, {%8,%9}, {%0,%1,%2,%3};" \
        : "+f"((acc)[0]), "+f"((acc)[1]), "+f"((acc)[2]), "+f"((acc)[3]) \
        : "r"((ar)[0]), "r"((ar)[1]), "r"((ar)[2]), "r"((ar)[3]), \
          "r"((br)[0]), "r"((br)[1]))

__global__ void __launch_bounds__(256, 2) gemm_f16()
{
    extern __shared__ char smem[];
    const uint32_t sb = smem_u32(smem);
    const int tid  = threadIdx.x;
    const int lane = tid & 31;
    const int warp = tid >> 5;
    const int wm   = warp >> 2;
    const int wn   = warp & 3;

    const int z = blockIdx.z;
    const __half* __restrict__ A = z ? g_hh  : g_xh;
    const __half* __restrict__ W = z ? g_whh : g_wih;
    __half* __restrict__ C       = z ? g_pre_hh : g_pre_ih;
    const int bm = blockIdx.y * BM;
    const int bn = blockIdx.x * BN;

    float acc[4][4][4];
#pragma unroll
    for (int a = 0; a < 4; a++)
#pragma unroll
        for (int b = 0; b < 4; b++)
#pragma unroll
            for (int d = 0; d < 4; d++) acc[a][b][d] = 0.f;

    const int lrow = tid >> 1;
    const int lcp  = (tid & 1) * 2;
    const __half* gA0 = A + (size_t)(bm + lrow) * KDIM + lcp * 8;
    const __half* gW0 = W + (size_t)(bn + lrow) * KDIM + lcp * 8;
    const uint32_t sA0 = sb + lrow * ROWB + lcp * 16;
    const uint32_t sB0 = sA0 + A_SM_BYTES;

    auto issue = [&](int kt) {
        const int buf = kt & (STAGES - 1);
        const size_t ko = (size_t)kt * BK;
        const uint32_t so = buf * STAGE_BYTES;
        cp16(sA0 + so,      gA0 + ko);
        cp16(sA0 + so + 16, gA0 + ko + 8);
        cp16(sB0 + so,      gW0 + ko);
        cp16(sB0 + so + 16, gW0 + ko + 8);
        asm volatile("cp.async.commit_group;");
    };

    issue(0); issue(1); issue(2);

    const int l15 = lane & 15, lhi = lane >> 4;
    const uint32_t aBase = sb + (wm * 64 + l15) * ROWB + lhi * 16;
    const uint32_t bBase = sb + A_SM_BYTES + (wn * 32 + l15) * ROWB + lhi * 16;

    asm volatile("cp.async.wait_group 1;");
    __syncthreads();

    uint32_t a0[4][4], b0[4][2];
#pragma unroll
    for (int mt = 0; mt < 4; mt++)
        LDSM_X4(a0[mt][0], a0[mt][1], a0[mt][2], a0[mt][3],
                aBase + mt * (16 * ROWB));
    LDSM_X4(b0[0][0], b0[1][0], b0[0][1], b0[1][1], bBase);
    LDSM_X4(b0[2][0], b0[3][0], b0[2][1], b0[3][1], bBase + 16 * ROWB);

    for (int kt = 0; kt < NK; kt++) {
        const uint32_t so  = (kt & (STAGES - 1)) * STAGE_BYTES;
        const uint32_t son = ((kt + 1) & (STAGES - 1)) * STAGE_BYTES;

        uint32_t a1[4][4], b1[4][2];
#pragma unroll
        for (int mt = 0; mt < 4; mt++)
            LDSM_X4(a1[mt][0], a1[mt][1], a1[mt][2], a1[mt][3],
                    aBase + so + mt * (16 * ROWB) + 32);
        LDSM_X4(b1[0][0], b1[1][0], b1[0][1], b1[1][1], bBase + so + 32);
        LDSM_X4(b1[2][0], b1[3][0], b1[2][1], b1[3][1],
                bBase + so + 16 * ROWB + 32);

#pragma unroll
        for (int mt = 0; mt < 4; mt++)
#pragma unroll
            for (int nt = 0; nt < 4; nt++)
                MMA16816(acc[mt][nt], a0[mt], b0[nt]);

        if (kt + 1 < NK) {
#pragma unroll
            for (int mt = 0; mt < 4; mt++)
                LDSM_X4(a0[mt][0], a0[mt][1], a0[mt][2], a0[mt][3],
                        aBase + son + mt * (16 * ROWB));
            LDSM_X4(b0[0][0], b0[1][0], b0[0][1], b0[1][1], bBase + son);
            LDSM_X4(b0[2][0], b0[3][0], b0[2][1], b0[3][1],
                    bBase + son + 16 * ROWB);
        }

#pragma unroll
        for (int mt = 0; mt < 4; mt++)
#pragma unroll
            for (int nt = 0; nt < 4; nt++)
                MMA16816(acc[mt][nt], a1[mt], b1[nt]);

        if (kt + 3 < NK) {
            issue(kt + 3);
            asm volatile("cp.async.wait_group 1;");
        } else {
            asm volatile("cp.async.wait_group 0;");
        }
        __syncthreads();
    }

#pragma unroll
    for (int mt = 0; mt < 4; mt++) {
#pragma unroll
        for (int nt = 0; nt < 4; nt++) {
            int gm = bm + wm * 64 + mt * 16 + (lane >> 2);
            int gn = bn + wn * 32 + nt * 8 + (lane & 3) * 2;
            *(__half2*)&C[(size_t)gm * NDIM + gn] =
                __floats2half2_rn(acc[mt][nt][0], acc[mt][nt][1]);
            *(__half2*)&C[(size_t)(gm + 8) * NDIM + gn] =
                __floats2half2_rn(acc[mt][nt][2], acc[mt][nt][3]);
        }
    }
}

// ---------------------------------------------------------------------------
// LayerNorm + LSTM cell epilogue.  One block per batch row, 256 threads.
// ALL activations via single MUFU.TANH approx.
// ---------------------------------------------------------------------------
__device__ __forceinline__ float tanh_ap(float x) {
    float y;
    asm("tanh.approx.f32 %0, %1;" : "=f"(y) : "f"(x));
    return y;
}
__device__ __forceinline__ float sigmoid_ap(float x) {   // 1 MUFU
    return fmaf(tanh_ap(0.5f * x), 0.5f, 0.5f);
}

__global__ void __launch_bounds__(256) ln_cell_kernel(
    const float* __restrict__ c_in,
    const float* __restrict__ b_ih,
    const float* __restrict__ gma,
    const float* __restrict__ bta,
    float* __restrict__ out)
{
    const int b   = blockIdx.x;
    const int tid = threadIdx.x;
    const int warp = tid >> 5, lane = tid & 31;

    __shared__ float s_ih[NDIM];
    __shared__ float s_hh[NDIM];
    __shared__ float stats[18];
    __shared__ float red[16];

    const uint4* pih = (const uint4*)(g_pre_ih + (size_t)b * NDIM);
    const uint4* phh = (const uint4*)(g_pre_hh + (size_t)b * NDIM);
    for (int i = tid; i < NDIM / 8; i += 256) {
        uint4 v = pih[i];
        const __half2* hp = (const __half2*)&v;
#pragma unroll
        for (int q = 0; q < 4; q++) {
            float2 f = __half22float2(hp[q]);
            s_ih[8 * i + 2 * q]     = f.x;
            s_ih[8 * i + 2 * q + 1] = f.y;
        }
        v = phh[i];
#pragma unroll
        for (int q = 0; q < 4; q++) {
            float2 f = __half22float2(hp[q]);
            s_hh[8 * i + 2 * q]     = f.x;
            s_hh[8 * i + 2 * q + 1] = f.y;
        }
    }
    __syncthreads();

    {
        const float* src = (warp & 1) ? s_hh : s_ih;
        const int gate = warp >> 1;
        float sum = 0.f, ss = 0.f;
        for (int j = lane; j < HDIM; j += 32) {
            float v = src[gate * HDIM + j];
            sum += v; ss += v * v;
        }
#pragma unroll
        for (int o = 16; o; o >>= 1) {
            sum += __shfl_xor_sync(0xffffffffu, sum, o);
            ss  += __shfl_xor_sync(0xffffffffu, ss,  o);
        }
        if (lane == 0) {
            float mu = sum * (1.0f / HDIM);
            stats[warp * 2]     = mu;
            stats[warp * 2 + 1] = ss * (1.0f / HDIM) - mu * mu;
        }
    }
    __syncthreads();

    float mu[8], rs[8];
#pragma unroll
    for (int t = 0; t < 8; t++) {
        mu[t] = stats[t * 2];
        rs[t] = rsqrtf(stats[t * 2 + 1] + 1e-5f);
    }

    float cvals[4], ovals[4];
    float csum = 0.f, css = 0.f;
#pragma unroll
    for (int ii = 0; ii < 4; ii++) {
        int j = tid + ii * 256;
        float gv[4];
#pragma unroll
        for (int g = 0; g < 4; g++) {
            int si = g * 2, sh = g * 2 + 1;
            float vih = s_ih[g * HDIM + j];
            float vhh = s_hh[g * HDIM + j];
            float li = gma[(2 * g) * HDIM + j] * (vih - mu[si]) * rs[si] + bta[(2 * g) * HDIM + j];
            float lh = gma[(2 * g + 1) * HDIM + j] * (vhh - mu[sh]) * rs[sh] + bta[(2 * g + 1) * HDIM + j];
            gv[g] = li + lh + b_ih[g * HDIM + j];
        }
        float ig = sigmoid_ap(gv[0]);
        float fg = sigmoid_ap(gv[1]);
        float ag = tanh_ap(gv[2]);
        float cn = fg * c_in[(size_t)b * HDIM + j] + ig * ag;
        cvals[ii] = cn;
        ovals[ii] = gv[3];
        csum += cn; css += cn * cn;
    }

#pragma unroll
    for (int o = 16; o; o >>= 1) {
        csum += __shfl_xor_sync(0xffffffffu, csum, o);
        css  += __shfl_xor_sync(0xffffffffu, css,  o);
    }
    if (lane == 0) { red[warp] = csum; red[8 + warp] = css; }
    __syncthreads();
    if (tid == 0) {
        float s = 0.f, q = 0.f;
#pragma unroll
        for (int k = 0; k < 8; k++) { s += red[k]; q += red[8 + k]; }
        float m = s * (1.0f / HDIM);
        stats[16] = m;
        stats[17] = q * (1.0f / HDIM) - m * m;
    }
    __syncthreads();

    const float cmu = stats[16];
    const float crs = rsqrtf(stats[17] + 1e-5f);
#pragma unroll
    for (int ii = 0; ii < 4; ii++) {
        int j = tid + ii * 256;
        float lnc = gma[8 * HDIM + j] * (cvals[ii] - cmu) * crs + bta[8 * HDIM + j];
        float hn = sigmoid_ap(ovals[ii]) * tanh_ap(lnc);   // 2 MUFU total
        out[(size_t)b * HDIM + j] = hn;
        out[(size_t)BATCH * HDIM + (size_t)b * HDIM + j] = cvals[ii];
    }
}

// ---------------------------------------------------------------------------
// kernel_launch
// ---------------------------------------------------------------------------
extern "C" void kernel_launch(void* const* d_in, const int* in_sizes, int n_in,
                              void* d_out, int out_size)
{
    const float* x   = (const float*)d_in[0];
    const float* h   = (const float*)d_in[1];
    const float* c   = (const float*)d_in[2];
    const float* wih = (const float*)d_in[3];
    const float* whh = (const float*)d_in[4];
    const float* bih = (const float*)d_in[5];
    const float* gma = (const float*)d_in[6];
    const float* bta = (const float*)d_in[7];
    float* out = (float*)d_out;

    dim3 cgrid(BATCH * KDIM / 16 / 256, 4);
    cvt_kernel<<<cgrid, 256>>>((const float4*)x, (const float4*)h,
                               (const float4*)wih, (const float4*)whh);

    cudaFuncSetAttribute(gemm_f16, cudaFuncAttributeMaxDynamicSharedMemorySize, SMEM_TOTAL);
    dim3 ggrid(NDIM / BN, BATCH / BM, 2);
    gemm_f16<<<ggrid, 256, SMEM_TOTAL>>>();

    ln_cell_kernel<<<BATCH, 256>>>(c, bih, gma, bta, out);
}

// round 12
// speedup vs baseline: 1.2720x; 1.0441x over previous
#include <cuda_runtime.h>
#include <cuda_fp16.h>
#include <cstdint>
#include <cstddef>

// Problem sizes (fixed)
#define BATCH 4096
#define HDIM  1024
#define KDIM  1024
#define NDIM  4096

// ---------------------------------------------------------------------------
// Scratch (device globals -- allocation is forbidden)
// ---------------------------------------------------------------------------
__device__ __align__(1024) __half g_xh [BATCH * KDIM];
__device__ __align__(1024) __half g_hh [BATCH * KDIM];
__device__ __align__(1024) __half g_wih[NDIM  * KDIM];
__device__ __align__(1024) __half g_whh[NDIM  * KDIM];
__device__ __align__(16) __half g_pre_ih[(size_t)BATCH * NDIM];   // fp16 pre-activations
__device__ __align__(16) __half g_pre_hh[(size_t)BATCH * NDIM];

// ---------------------------------------------------------------------------
// fp32 -> fp16 preconversion.  Each thread: 16 floats (4 indep float4 loads).
// ---------------------------------------------------------------------------
__global__ void __launch_bounds__(256) cvt_kernel(
    const float4* __restrict__ x, const float4* __restrict__ h,
    const float4* __restrict__ wih, const float4* __restrict__ whh)
{
    int i = blockIdx.x * blockDim.x + threadIdx.x;
    const float4* src; __half* dst;
    switch (blockIdx.y) {
        case 0:  src = x;   dst = g_xh;  break;
        case 1:  src = h;   dst = g_hh;  break;
        case 2:  src = wih; dst = g_wih; break;
        default: src = whh; dst = g_whh; break;
    }
    float4 v0 = src[4 * i];
    float4 v1 = src[4 * i + 1];
    float4 v2 = src[4 * i + 2];
    float4 v3 = src[4 * i + 3];
    __half2 o[8];
    o[0] = __floats2half2_rn(v0.x, v0.y);  o[1] = __floats2half2_rn(v0.z, v0.w);
    o[2] = __floats2half2_rn(v1.x, v1.y);  o[3] = __floats2half2_rn(v1.z, v1.w);
    o[4] = __floats2half2_rn(v2.x, v2.y);  o[5] = __floats2half2_rn(v2.z, v2.w);
    o[6] = __floats2half2_rn(v3.x, v3.y);  o[7] = __floats2half2_rn(v3.z, v3.w);
    uint4* d = (uint4*)(dst + 16 * (size_t)i);
    d[0] = ((uint4*)o)[0];
    d[1] = ((uint4*)o)[1];
}

// ---------------------------------------------------------------------------
// fp16 GEMM: C = A @ W^T.  128x128x32 tile, 64x32 warp tile, 4-stage cp.async,
// single sync/window, cross-barrier LDSM preload.   (R9 schedule, FROZEN)
// ---------------------------------------------------------------------------
#define BM 128
#define BN 128
#define BK 32
#define ROWB 80
#define STAGES 4
#define NK (KDIM / BK)
#define A_SM_BYTES (BM * ROWB)
#define STAGE_BYTES (2 * A_SM_BYTES)
#define SMEM_TOTAL (STAGES * STAGE_BYTES)

__device__ __forceinline__ uint32_t smem_u32(const void* p) {
    uint32_t a;
    asm("{ .reg .u64 t; cvta.to.shared.u64 t, %1; cvt.u32.u64 %0, t; }" : "=r"(a) : "l"(p));
    return a;
}
__device__ __forceinline__ void cp16(uint32_t smem, const void* gmem) {
    asm volatile("cp.async.cg.shared.global [%0], [%1], 16;" :: "r"(smem), "l"(gmem));
}
#define LDSM_X4(r0, r1, r2, r3, addr) \
    asm volatile("ldmatrix.sync.aligned.m8n8.x4.shared.b16 {%0,%1,%2,%3}, [%4];" \
        : "=r"(r0), "=r"(r1), "=r"(r2), "=r"(r3) : "r"(addr))
#define MMA16816(acc, ar, br) \
    asm volatile( \
        "mma.sync.aligned.m16n8k16.row.col.f32.f16.f16.f32 " \
        "{%0,%1,%2,%3}, {%4,%5,%6,%7}, {%8,%9}, {%0,%1,%2,%3};" \
        : "+f"((acc)[0]), "+f"((acc)[1]), "+f"((acc)[2]), "+f"((acc)[3]) \
        : "r"((ar)[0]), "r"((ar)[1]), "r"((ar)[2]), "r"((ar)[3]), \
          "r"((br)[0]), "r"((br)[1]))

__global__ void __launch_bounds__(256, 2) gemm_f16()
{
    extern __shared__ char smem[];
    const uint32_t sb = smem_u32(smem);
    const int tid  = threadIdx.x;
    const int lane = tid & 31;
    const int warp = tid >> 5;
    const int wm   = warp >> 2;
    const int wn   = warp & 3;

    const int z = blockIdx.z;
    const __half* __restrict__ A = z ? g_hh  : g_xh;
    const __half* __restrict__ W = z ? g_whh : g_wih;
    __half* __restrict__ C       = z ? g_pre_hh : g_pre_ih;
    const int bm = blockIdx.y * BM;
    const int bn = blockIdx.x * BN;

    float acc[4][4][4];
#pragma unroll
    for (int a = 0; a < 4; a++)
#pragma unroll
        for (int b = 0; b < 4; b++)
#pragma unroll
            for (int d = 0; d < 4; d++) acc[a][b][d] = 0.f;

    const int lrow = tid >> 1;
    const int lcp  = (tid & 1) * 2;
    const __half* gA0 = A + (size_t)(bm + lrow) * KDIM + lcp * 8;
    const __half* gW0 = W + (size_t)(bn + lrow) * KDIM + lcp * 8;
    const uint32_t sA0 = sb + lrow * ROWB + lcp * 16;
    const uint32_t sB0 = sA0 + A_SM_BYTES;

    auto issue = [&](int kt) {
        const int buf = kt & (STAGES - 1);
        const size_t ko = (size_t)kt * BK;
        const uint32_t so = buf * STAGE_BYTES;
        cp16(sA0 + so,      gA0 + ko);
        cp16(sA0 + so + 16, gA0 + ko + 8);
        cp16(sB0 + so,      gW0 + ko);
        cp16(sB0 + so + 16, gW0 + ko + 8);
        asm volatile("cp.async.commit_group;");
    };

    issue(0); issue(1); issue(2);

    const int l15 = lane & 15, lhi = lane >> 4;
    const uint32_t aBase = sb + (wm * 64 + l15) * ROWB + lhi * 16;
    const uint32_t bBase = sb + A_SM_BYTES + (wn * 32 + l15) * ROWB + lhi * 16;

    asm volatile("cp.async.wait_group 1;");
    __syncthreads();

    uint32_t a0[4][4], b0[4][2];
#pragma unroll
    for (int mt = 0; mt < 4; mt++)
        LDSM_X4(a0[mt][0], a0[mt][1], a0[mt][2], a0[mt][3],
                aBase + mt * (16 * ROWB));
    LDSM_X4(b0[0][0], b0[1][0], b0[0][1], b0[1][1], bBase);
    LDSM_X4(b0[2][0], b0[3][0], b0[2][1], b0[3][1], bBase + 16 * ROWB);

    for (int kt = 0; kt < NK; kt++) {
        const uint32_t so  = (kt & (STAGES - 1)) * STAGE_BYTES;
        const uint32_t son = ((kt + 1) & (STAGES - 1)) * STAGE_BYTES;

        uint32_t a1[4][4], b1[4][2];
#pragma unroll
        for (int mt = 0; mt < 4; mt++)
            LDSM_X4(a1[mt][0], a1[mt][1], a1[mt][2], a1[mt][3],
                    aBase + so + mt * (16 * ROWB) + 32);
        LDSM_X4(b1[0][0], b1[1][0], b1[0][1], b1[1][1], bBase + so + 32);
        LDSM_X4(b1[2][0], b1[3][0], b1[2][1], b1[3][1],
                bBase + so + 16 * ROWB + 32);

#pragma unroll
        for (int mt = 0; mt < 4; mt++)
#pragma unroll
            for (int nt = 0; nt < 4; nt++)
                MMA16816(acc[mt][nt], a0[mt], b0[nt]);

        if (kt + 1 < NK) {
#pragma unroll
            for (int mt = 0; mt < 4; mt++)
                LDSM_X4(a0[mt][0], a0[mt][1], a0[mt][2], a0[mt][3],
                        aBase + son + mt * (16 * ROWB));
            LDSM_X4(b0[0][0], b0[1][0], b0[0][1], b0[1][1], bBase + son);
            LDSM_X4(b0[2][0], b0[3][0], b0[2][1], b0[3][1],
                    bBase + son + 16 * ROWB);
        }

#pragma unroll
        for (int mt = 0; mt < 4; mt++)
#pragma unroll
            for (int nt = 0; nt < 4; nt++)
                MMA16816(acc[mt][nt], a1[mt], b1[nt]);

        if (kt + 3 < NK) {
            issue(kt + 3);
            asm volatile("cp.async.wait_group 1;");
        } else {
            asm volatile("cp.async.wait_group 0;");
        }
        __syncthreads();
    }

#pragma unroll
    for (int mt = 0; mt < 4; mt++) {
#pragma unroll
        for (int nt = 0; nt < 4; nt++) {
            int gm = bm + wm * 64 + mt * 16 + (lane >> 2);
            int gn = bn + wn * 32 + nt * 8 + (lane & 3) * 2;
            *(__half2*)&C[(size_t)gm * NDIM + gn] =
                __floats2half2_rn(acc[mt][nt][0], acc[mt][nt][1]);
            *(__half2*)&C[(size_t)(gm + 8) * NDIM + gn] =
                __floats2half2_rn(acc[mt][nt][2], acc[mt][nt][3]);
        }
    }
}

// ---------------------------------------------------------------------------
// LayerNorm + LSTM cell: single-pass, register-resident.
// One block per batch row, 256 threads; thread t owns j = 4t..4t+3 for ALL
// gates/sources.  Stats partials accumulated during load, block-reduced via
// a 16KB psums array (warp w reduces stat-pair w).  No value smem arrays.
// ---------------------------------------------------------------------------
__device__ __forceinline__ float tanh_ap(float x) {
    float y;
    asm("tanh.approx.f32 %0, %1;" : "=f"(y) : "f"(x));
    return y;
}
__device__ __forceinline__ float sigmoid_ap(float x) {   // 1 MUFU
    return fmaf(tanh_ap(0.5f * x), 0.5f, 0.5f);
}

__global__ void __launch_bounds__(256) ln_cell_kernel(
    const float* __restrict__ c_in,
    const float* __restrict__ b_ih,
    const float* __restrict__ gma,
    const float* __restrict__ bta,
    float* __restrict__ out)
{
    const int b    = blockIdx.x;
    const int tid  = threadIdx.x;
    const int warp = tid >> 5, lane = tid & 31;

    __shared__ float psums[16][256];   // [2*s + {0:sum,1:ss}][thread]
    __shared__ float stats[18];        // (mu,var) x 8 gate-LNs + (mu,var) c
    __shared__ float red[16];

    // ---- load 32 halves (4 j x 4 gates x 2 src) + partial stats ----
    const uint2* pih2 = (const uint2*)(g_pre_ih + (size_t)b * NDIM);
    const uint2* phh2 = (const uint2*)(g_pre_hh + (size_t)b * NDIM);

    float vih[4][4], vhh[4][4];        // [g][jj]
    float sum[8], ssq[8];              // s = 2g (ih), 2g+1 (hh)
#pragma unroll
    for (int g = 0; g < 4; g++) {
        uint2 ri = pih2[g * 256 + tid];
        uint2 rh = phh2[g * 256 + tid];
        float2 f0 = __half22float2(*(__half2*)&ri.x);
        float2 f1 = __half22float2(*(__half2*)&ri.y);
        vih[g][0] = f0.x; vih[g][1] = f0.y; vih[g][2] = f1.x; vih[g][3] = f1.y;
        float si = f0.x + f0.y + f1.x + f1.y;
        float qi = f0.x*f0.x + f0.y*f0.y + f1.x*f1.x + f1.y*f1.y;
        sum[2*g] = si; ssq[2*g] = qi;
        f0 = __half22float2(*(__half2*)&rh.x);
        f1 = __half22float2(*(__half2*)&rh.y);
        vhh[g][0] = f0.x; vhh[g][1] = f0.y; vhh[g][2] = f1.x; vhh[g][3] = f1.y;
        float sh = f0.x + f0.y + f1.x + f1.y;
        float qh = f0.x*f0.x + f0.y*f0.y + f1.x*f1.x + f1.y*f1.y;
        sum[2*g+1] = sh; ssq[2*g+1] = qh;
    }

#pragma unroll
    for (int s = 0; s < 8; s++) {
        psums[2*s][tid]     = sum[s];
        psums[2*s + 1][tid] = ssq[s];
    }
    __syncthreads();

    // ---- warp w reduces stat-pair w (sum + ss over 256 threads) ----
    {
        float as = 0.f, aq = 0.f;
#pragma unroll
        for (int k = 0; k < 8; k++) {
            as += psums[2*warp][lane + 32*k];
            aq += psums[2*warp + 1][lane + 32*k];
        }
#pragma unroll
        for (int o = 16; o; o >>= 1) {
            as += __shfl_xor_sync(0xffffffffu, as, o);
            aq += __shfl_xor_sync(0xffffffffu, aq, o);
        }
        if (lane == 0) {
            float mu = as * (1.0f / HDIM);
            stats[2*warp]     = mu;
            stats[2*warp + 1] = aq * (1.0f / HDIM) - mu * mu;
        }
    }
    __syncthreads();

    float mu[8], rs[8];
#pragma unroll
    for (int t = 0; t < 8; t++) {
        mu[t] = stats[2*t];
        rs[t] = rsqrtf(stats[2*t + 1] + 1e-5f);
    }

    // ---- gates (LN + bias), cell update, c stats ----
    const float4* g4  = (const float4*)gma;
    const float4* bt4 = (const float4*)bta;
    const float4* bi4 = (const float4*)b_ih;

    float act[4][4];   // [g][jj]
#pragma unroll
    for (int g = 0; g < 4; g++) {
        float4 Gi = g4 [(2*g) * 256 + tid];
        float4 Bi = bt4[(2*g) * 256 + tid];
        float4 Gh = g4 [(2*g + 1) * 256 + tid];
        float4 Bh = bt4[(2*g + 1) * 256 + tid];
        float4 Fb = bi4[g * 256 + tid];
        const float* gi = (const float*)&Gi;  const float* bi = (const float*)&Bi;
        const float* gh = (const float*)&Gh;  const float* bh = (const float*)&Bh;
        const float* fb = (const float*)&Fb;
#pragma unroll
        for (int jj = 0; jj < 4; jj++) {
            float li = gi[jj] * (vih[g][jj] - mu[2*g])     * rs[2*g]     + bi[jj];
            float lh = gh[jj] * (vhh[g][jj] - mu[2*g + 1]) * rs[2*g + 1] + bh[jj];
            act[g][jj] = li + lh + fb[jj];
        }
    }

    float4 c4 = ((const float4*)(c_in + (size_t)b * HDIM))[tid];
    const float* cp = (const float*)&c4;
    float cvals[4], ovals[4];
    float csum = 0.f, css = 0.f;
#pragma unroll
    for (int jj = 0; jj < 4; jj++) {
        float ig = sigmoid_ap(act[0][jj]);
        float fg = sigmoid_ap(act[1][jj]);
        float ag = tanh_ap(act[2][jj]);
        float cn = fg * cp[jj] + ig * ag;
        cvals[jj] = cn;
        ovals[jj] = act[3][jj];
        csum += cn; css += cn * cn;
    }

#pragma unroll
    for (int o = 16; o; o >>= 1) {
        csum += __shfl_xor_sync(0xffffffffu, csum, o);
        css  += __shfl_xor_sync(0xffffffffu, css,  o);
    }
    if (lane == 0) { red[warp] = csum; red[8 + warp] = css; }
    __syncthreads();
    if (tid == 0) {
        float s = 0.f, q = 0.f;
#pragma unroll
        for (int k = 0; k < 8; k++) { s += red[k]; q += red[8 + k]; }
        float m = s * (1.0f / HDIM);
        stats[16] = m;
        stats[17] = q * (1.0f / HDIM) - m * m;
    }
    __syncthreads();

    const float cmu = stats[16];
    const float crs = rsqrtf(stats[17] + 1e-5f);

    float4 Gc = g4 [8 * 256 + tid];
    float4 Bc = bt4[8 * 256 + tid];
    const float* gc = (const float*)&Gc;
    const float* bc = (const float*)&Bc;

    float4 hn4, cn4;
    float* hn = (float*)&hn4;  float* cn = (float*)&cn4;
#pragma unroll
    for (int jj = 0; jj < 4; jj++) {
        float lnc = gc[jj] * (cvals[jj] - cmu) * crs + bc[jj];
        hn[jj] = sigmoid_ap(ovals[jj]) * tanh_ap(lnc);
        cn[jj] = cvals[jj];
    }
    float4* out4 = (float4*)out;
    out4[(size_t)b * 256 + tid] = hn4;                                  // h_new
    out4[(size_t)BATCH * 256 + (size_t)b * 256 + tid] = cn4;            // c_new
}

// ---------------------------------------------------------------------------
// kernel_launch
// ---------------------------------------------------------------------------
extern "C" void kernel_launch(void* const* d_in, const int* in_sizes, int n_in,
                              void* d_out, int out_size)
{
    const float* x   = (const float*)d_in[0];
    const float* h   = (const float*)d_in[1];
    const float* c   = (const float*)d_in[2];
    const float* wih = (const float*)d_in[3];
    const float* whh = (const float*)d_in[4];
    const float* bih = (const float*)d_in[5];
    const float* gma = (const float*)d_in[6];
    const float* bta = (const float*)d_in[7];
    float* out = (float*)d_out;

    dim3 cgrid(BATCH * KDIM / 16 / 256, 4);
    cvt_kernel<<<cgrid, 256>>>((const float4*)x, (const float4*)h,
                               (const float4*)wih, (const float4*)whh);

    cudaFuncSetAttribute(gemm_f16, cudaFuncAttributeMaxDynamicSharedMemorySize, SMEM_TOTAL);
    dim3 ggrid(NDIM / BN, BATCH / BM, 2);
    gemm_f16<<<ggrid, 256, SMEM_TOTAL>>>();

    ln_cell_kernel<<<BATCH, 256>>>(c, bih, gma, bta, out);
}

// round 14
// speedup vs baseline: 1.3983x; 1.0992x over previous
#include <cuda_runtime.h>
#include <cuda_fp16.h>
#include <cstdint>
#include <cstddef>

// Problem sizes (fixed)
#define BATCH 4096
#define HDIM  1024
#define KDIM  1024
#define NDIM  4096

// ---------------------------------------------------------------------------
// Scratch (device globals -- allocation is forbidden)
// ---------------------------------------------------------------------------
__device__ __align__(1024) __half g_xh [BATCH * KDIM];
__device__ __align__(1024) __half g_hh [BATCH * KDIM];
__device__ __align__(1024) __half g_wih[NDIM  * KDIM];
__device__ __align__(1024) __half g_whh[NDIM  * KDIM];
__device__ __align__(16) __half g_pre_ih[(size_t)BATCH * NDIM];   // fp16 pre-activations
__device__ __align__(16) __half g_pre_hh[(size_t)BATCH * NDIM];

// ---------------------------------------------------------------------------
// fp32 -> fp16 preconversion.  Each thread: 16 floats (4 indep float4 loads).
// ---------------------------------------------------------------------------
__global__ void __launch_bounds__(256) cvt_kernel(
    const float4* __restrict__ x, const float4* __restrict__ h,
    const float4* __restrict__ wih, const float4* __restrict__ whh)
{
    int i = blockIdx.x * blockDim.x + threadIdx.x;
    const float4* src; __half* dst;
    switch (blockIdx.y) {
        case 0:  src = x;   dst = g_xh;  break;
        case 1:  src = h;   dst = g_hh;  break;
        case 2:  src = wih; dst = g_wih; break;
        default: src = whh; dst = g_whh; break;
    }
    float4 v0 = src[4 * i];
    float4 v1 = src[4 * i + 1];
    float4 v2 = src[4 * i + 2];
    float4 v3 = src[4 * i + 3];
    __half2 o[8];
    o[0] = __floats2half2_rn(v0.x, v0.y);  o[1] = __floats2half2_rn(v0.z, v0.w);
    o[2] = __floats2half2_rn(v1.x, v1.y);  o[3] = __floats2half2_rn(v1.z, v1.w);
    o[4] = __floats2half2_rn(v2.x, v2.y);  o[5] = __floats2half2_rn(v2.z, v2.w);
    o[6] = __floats2half2_rn(v3.x, v3.y);  o[7] = __floats2half2_rn(v3.z, v3.w);
    uint4* d = (uint4*)(dst + 16 * (size_t)i);
    d[0] = ((uint4*)o)[0];
    d[1] = ((uint4*)o)[1];
}

// ---------------------------------------------------------------------------
// fp16 GEMM: C = A @ W^T.  128x128x32 tile, 64x32 warp tile, 4-stage cp.async,
// per-stage mbarrier pipeline (cp.async.mbarrier.arrive.NOINC), cross-barrier
// LDSM preload.  grid = (N/128, M/128, 2).  block = 256 (8 warps, 2 CTA/SM)
// ---------------------------------------------------------------------------
#define BM 128
#define BN 128
#define BK 32
#define ROWB 80
#define STAGES 4
#define NK (KDIM / BK)
#define A_SM_BYTES (BM * ROWB)
#define STAGE_BYTES (2 * A_SM_BYTES)       // 20480
#define TILES_BYTES (STAGES * STAGE_BYTES) // 81920
#define SMEM_TOTAL (TILES_BYTES + 128)     // + mbarriers

__device__ __forceinline__ uint32_t smem_u32(const void* p) {
    uint32_t a;
    asm("{ .reg .u64 t; cvta.to.shared.u64 t, %1; cvt.u32.u64 %0, t; }" : "=r"(a) : "l"(p));
    return a;
}
__device__ __forceinline__ void cp16(uint32_t smem, const void* gmem) {
    asm volatile("cp.async.cg.shared.global [%0], [%1], 16;" :: "r"(smem), "l"(gmem));
}
#define LDSM_X4(r0, r1, r2, r3, addr) \
    asm volatile("ldmatrix.sync.aligned.m8n8.x4.shared.b16 {%0,%1,%2,%3}, [%4];" \
        : "=r"(r0), "=r"(r1), "=r"(r2), "=r"(r3) : "r"(addr))
#define MMA16816(acc, ar, br) \
    asm volatile( \
        "mma.sync.aligned.m16n8k16.row.col.f32.f16.f16.f32 " \
        "{%0,%1,%2,%3}, {%4,%5,%6,%7}, {%8,%9}, {%0,%1,%2,%3};" \
        : "+f"((acc)[0]), "+f"((acc)[1]), "+f"((acc)[2]), "+f"((acc)[3]) \
        : "r"((ar)[0]), "r"((ar)[1]), "r"((ar)[2]), "r"((ar)[3]), \
          "r"((br)[0]), "r"((br)[1]))

#define MBAR_INIT(addr, cnt) \
    asm volatile("mbarrier.init.shared.b64 [%0], %1;" :: "r"(addr), "r"(cnt) : "memory")
#define MBAR_ARRIVE(addr) \
    asm volatile("mbarrier.arrive.shared.b64 _, [%0];" :: "r"(addr) : "memory")
// NOINC: each thread contributes exactly one arrival when its prior cp.asyncs
// complete (default variant is inc-then-arrive = net zero -> R13 deadlock).
#define CPASYNC_MBAR_ARRIVE(addr) \
    asm volatile("cp.async.mbarrier.arrive.noinc.shared.b64 [%0];" :: "r"(addr) : "memory")
#define MBAR_WAIT(addr, ph) do { \
    uint32_t _m = (addr); uint32_t _p = (ph); uint32_t _d; \
    asm volatile("{\n\t.reg .pred p;\n\t" \
        "mbarrier.try_wait.parity.acquire.cta.shared::cta.b64 p, [%1], %2;\n\t" \
        "selp.b32 %0, 1, 0, p;\n\t}" : "=r"(_d) : "r"(_m), "r"(_p) : "memory"); \
    if (!_d) { \
        asm volatile("{\n\t.reg .pred P1;\n\t" \
            "WL_%=:\n\t" \
            "mbarrier.try_wait.parity.acquire.cta.shared::cta.b64 P1, [%0], %1, 0x989680;\n\t" \
            "@P1 bra.uni WD_%=;\n\t" \
            "bra.uni WL_%=;\n\t" \
            "WD_%=:\n\t}" :: "r"(_m), "r"(_p) : "memory"); \
    } \
} while (0)

__global__ void __launch_bounds__(256, 2) gemm_f16()
{
    extern __shared__ char smem[];
    const uint32_t sb = smem_u32(smem);
    const uint32_t mb_full  = sb + TILES_BYTES;        // 4 x 8B
    const uint32_t mb_empty = sb + TILES_BYTES + 32;   // 4 x 8B
    const int tid  = threadIdx.x;
    const int lane = tid & 31;
    const int warp = tid >> 5;
    const int wm   = warp >> 2;
    const int wn   = warp & 3;

    const int z = blockIdx.z;
    const __half* __restrict__ A = z ? g_hh  : g_xh;
    const __half* __restrict__ W = z ? g_whh : g_wih;
    __half* __restrict__ C       = z ? g_pre_hh : g_pre_ih;
    const int bm = blockIdx.y * BM;
    const int bn = blockIdx.x * BN;

    if (tid == 0) {
#pragma unroll
        for (int s = 0; s < STAGES; s++) {
            MBAR_INIT(mb_full  + 8 * s, 256);   // one noinc-arrive per thread
            MBAR_INIT(mb_empty + 8 * s, 8);     // one arrive per warp
        }
    }
    __syncthreads();    // only block-wide sync (barrier init visibility)

    float acc[4][4][4];
#pragma unroll
    for (int a = 0; a < 4; a++)
#pragma unroll
        for (int b = 0; b < 4; b++)
#pragma unroll
            for (int d = 0; d < 4; d++) acc[a][b][d] = 0.f;

    const int lrow = tid >> 1;
    const int lcp  = (tid & 1) * 2;
    const __half* gA0 = A + (size_t)(bm + lrow) * KDIM + lcp * 8;
    const __half* gW0 = W + (size_t)(bn + lrow) * KDIM + lcp * 8;
    const uint32_t sA0 = sb + lrow * ROWB + lcp * 16;
    const uint32_t sB0 = sA0 + A_SM_BYTES;

    // produce tile t into stage t&3, then arm full barrier (noinc arrive)
    auto issue = [&](int t) {
        const size_t ko = (size_t)t * BK;
        const uint32_t so = (t & (STAGES - 1)) * STAGE_BYTES;
        cp16(sA0 + so,      gA0 + ko);
        cp16(sA0 + so + 16, gA0 + ko + 8);
        cp16(sB0 + so,      gW0 + ko);
        cp16(sB0 + so + 16, gW0 + ko + 8);
        CPASYNC_MBAR_ARRIVE(mb_full + 8 * (t & (STAGES - 1)));
    };

    issue(0); issue(1); issue(2);   // stages known-empty: no wait

    const int l15 = lane & 15, lhi = lane >> 4;
    const uint32_t aBase = sb + (wm * 64 + l15) * ROWB + lhi * 16;
    const uint32_t bBase = sb + A_SM_BYTES + (wn * 32 + l15) * ROWB + lhi * 16;

    // wait tile 0 full, preload its ks0 fragments
    MBAR_WAIT(mb_full + 0, 0);
    uint32_t a0[4][4], b0[4][2];
#pragma unroll
    for (int mt = 0; mt < 4; mt++)
        LDSM_X4(a0[mt][0], a0[mt][1], a0[mt][2], a0[mt][3],
                aBase + mt * (16 * ROWB));
    LDSM_X4(b0[0][0], b0[1][0], b0[0][1], b0[1][1], bBase);
    LDSM_X4(b0[2][0], b0[3][0], b0[2][1], b0[3][1], bBase + 16 * ROWB);

    for (int kt = 0; kt < NK; kt++) {
        const uint32_t so  = (kt & (STAGES - 1)) * STAGE_BYTES;
        const uint32_t son = ((kt + 1) & (STAGES - 1)) * STAGE_BYTES;

        // LDSM ks1 of tile kt
        uint32_t a1[4][4], b1[4][2];
#pragma unroll
        for (int mt = 0; mt < 4; mt++)
            LDSM_X4(a1[mt][0], a1[mt][1], a1[mt][2], a1[mt][3],
                    aBase + so + mt * (16 * ROWB) + 32);
        LDSM_X4(b1[0][0], b1[1][0], b1[0][1], b1[1][1], bBase + so + 32);
        LDSM_X4(b1[2][0], b1[3][0], b1[2][1], b1[3][1],
                bBase + so + 16 * ROWB + 32);

        // MMA ks0 on preloaded fragments
#pragma unroll
        for (int mt = 0; mt < 4; mt++)
#pragma unroll
            for (int nt = 0; nt < 4; nt++)
                MMA16816(acc[mt][nt], a0[mt], b0[nt]);

        // preload ks0 of tile kt+1 (wait its full barrier; usually ready)
        if (kt + 1 < NK) {
            MBAR_WAIT(mb_full + 8 * ((kt + 1) & (STAGES - 1)),
                      ((kt + 1) >> 2) & 1);
#pragma unroll
            for (int mt = 0; mt < 4; mt++)
                LDSM_X4(a0[mt][0], a0[mt][1], a0[mt][2], a0[mt][3],
                        aBase + son + mt * (16 * ROWB));
            LDSM_X4(b0[0][0], b0[1][0], b0[0][1], b0[1][1], bBase + son);
            LDSM_X4(b0[2][0], b0[3][0], b0[2][1], b0[3][1],
                    bBase + son + 16 * ROWB);
        }

        // MMA ks1
#pragma unroll
        for (int mt = 0; mt < 4; mt++)
#pragma unroll
            for (int nt = 0; nt < 4; nt++)
                MMA16816(acc[mt][nt], a1[mt], b1[nt]);

        // this warp is done reading stage kt
        if (lane == 0) MBAR_ARRIVE(mb_empty + 8 * (kt & (STAGES - 1)));

        // produce tile kt+3 (wait for its stage to be drained)
        if (kt + 3 < NK) {
            const int t = kt + 3;
            if (t >= STAGES)
                MBAR_WAIT(mb_empty + 8 * (t & (STAGES - 1)),
                          ((t - STAGES) >> 2) & 1);
            issue(t);
        }
    }

    // epilogue: fp32 acc -> fp16 store (no sync needed; warps independent)
#pragma unroll
    for (int mt = 0; mt < 4; mt++) {
#pragma unroll
        for (int nt = 0; nt < 4; nt++) {
            int gm = bm + wm * 64 + mt * 16 + (lane >> 2);
            int gn = bn + wn * 32 + nt * 8 + (lane & 3) * 2;
            *(__half2*)&C[(size_t)gm * NDIM + gn] =
                __floats2half2_rn(acc[mt][nt][0], acc[mt][nt][1]);
            *(__half2*)&C[(size_t)(gm + 8) * NDIM + gn] =
                __floats2half2_rn(acc[mt][nt][2], acc[mt][nt][3]);
        }
    }
}

// ---------------------------------------------------------------------------
// LayerNorm + LSTM cell: single-pass, register-resident.  (R12, FROZEN)
// ---------------------------------------------------------------------------
__device__ __forceinline__ float tanh_ap(float x) {
    float y;
    asm("tanh.approx.f32 %0, %1;" : "=f"(y) : "f"(x));
    return y;
}
__device__ __forceinline__ float sigmoid_ap(float x) {
    return fmaf(tanh_ap(0.5f * x), 0.5f, 0.5f);
}

__global__ void __launch_bounds__(256) ln_cell_kernel(
    const float* __restrict__ c_in,
    const float* __restrict__ b_ih,
    const float* __restrict__ gma,
    const float* __restrict__ bta,
    float* __restrict__ out)
{
    const int b    = blockIdx.x;
    const int tid  = threadIdx.x;
    const int warp = tid >> 5, lane = tid & 31;

    __shared__ float psums[16][256];
    __shared__ float stats[18];
    __shared__ float red[16];

    const uint2* pih2 = (const uint2*)(g_pre_ih + (size_t)b * NDIM);
    const uint2* phh2 = (const uint2*)(g_pre_hh + (size_t)b * NDIM);

    float vih[4][4], vhh[4][4];
    float sum[8], ssq[8];
#pragma unroll
    for (int g = 0; g < 4; g++) {
        uint2 ri = pih2[g * 256 + tid];
        uint2 rh = phh2[g * 256 + tid];
        float2 f0 = __half22float2(*(__half2*)&ri.x);
        float2 f1 = __half22float2(*(__half2*)&ri.y);
        vih[g][0] = f0.x; vih[g][1] = f0.y; vih[g][2] = f1.x; vih[g][3] = f1.y;
        sum[2*g] = f0.x + f0.y + f1.x + f1.y;
        ssq[2*g] = f0.x*f0.x + f0.y*f0.y + f1.x*f1.x + f1.y*f1.y;
        f0 = __half22float2(*(__half2*)&rh.x);
        f1 = __half22float2(*(__half2*)&rh.y);
        vhh[g][0] = f0.x; vhh[g][1] = f0.y; vhh[g][2] = f1.x; vhh[g][3] = f1.y;
        sum[2*g+1] = f0.x + f0.y + f1.x + f1.y;
        ssq[2*g+1] = f0.x*f0.x + f0.y*f0.y + f1.x*f1.x + f1.y*f1.y;
    }

#pragma unroll
    for (int s = 0; s < 8; s++) {
        psums[2*s][tid]     = sum[s];
        psums[2*s + 1][tid] = ssq[s];
    }
    __syncthreads();

    {
        float as = 0.f, aq = 0.f;
#pragma unroll
        for (int k = 0; k < 8; k++) {
            as += psums[2*warp][lane + 32*k];
            aq += psums[2*warp + 1][lane + 32*k];
        }
#pragma unroll
        for (int o = 16; o; o >>= 1) {
            as += __shfl_xor_sync(0xffffffffu, as, o);
            aq += __shfl_xor_sync(0xffffffffu, aq, o);
        }
        if (lane == 0) {
            float mu = as * (1.0f / HDIM);
            stats[2*warp]     = mu;
            stats[2*warp + 1] = aq * (1.0f / HDIM) - mu * mu;
        }
    }
    __syncthreads();

    float mu[8], rs[8];
#pragma unroll
    for (int t = 0; t < 8; t++) {
        mu[t] = stats[2*t];
        rs[t] = rsqrtf(stats[2*t + 1] + 1e-5f);
    }

    const float4* g4  = (const float4*)gma;
    const float4* bt4 = (const float4*)bta;
    const float4* bi4 = (const float4*)b_ih;

    float act[4][4];
#pragma unroll
    for (int g = 0; g < 4; g++) {
        float4 Gi = g4 [(2*g) * 256 + tid];
        float4 Bi = bt4[(2*g) * 256 + tid];
        float4 Gh = g4 [(2*g + 1) * 256 + tid];
        float4 Bh = bt4[(2*g + 1) * 256 + tid];
        float4 Fb = bi4[g * 256 + tid];
        const float* gi = (const float*)&Gi;  const float* bi = (const float*)&Bi;
        const float* gh = (const float*)&Gh;  const float* bh = (const float*)&Bh;
        const float* fb = (const float*)&Fb;
#pragma unroll
        for (int jj = 0; jj < 4; jj++) {
            float li = gi[jj] * (vih[g][jj] - mu[2*g])     * rs[2*g]     + bi[jj];
            float lh = gh[jj] * (vhh[g][jj] - mu[2*g + 1]) * rs[2*g + 1] + bh[jj];
            act[g][jj] = li + lh + fb[jj];
        }
    }

    float4 c4 = ((const float4*)(c_in + (size_t)b * HDIM))[tid];
    const float* cp = (const float*)&c4;
    float cvals[4], ovals[4];
    float csum = 0.f, css = 0.f;
#pragma unroll
    for (int jj = 0; jj < 4; jj++) {
        float ig = sigmoid_ap(act[0][jj]);
        float fg = sigmoid_ap(act[1][jj]);
        float ag = tanh_ap(act[2][jj]);
        float cn = fg * cp[jj] + ig * ag;
        cvals[jj] = cn;
        ovals[jj] = act[3][jj];
        csum += cn; css += cn * cn;
    }

#pragma unroll
    for (int o = 16; o; o >>= 1) {
        csum += __shfl_xor_sync(0xffffffffu, csum, o);
        css  += __shfl_xor_sync(0xffffffffu, css,  o);
    }
    if (lane == 0) { red[warp] = csum; red[8 + warp] = css; }
    __syncthreads();
    if (tid == 0) {
        float s = 0.f, q = 0.f;
#pragma unroll
        for (int k = 0; k < 8; k++) { s += red[k]; q += red[8 + k]; }
        float m = s * (1.0f / HDIM);
        stats[16] = m;
        stats[17] = q * (1.0f / HDIM) - m * m;
    }
    __syncthreads();

    const float cmu = stats[16];
    const float crs = rsqrtf(stats[17] + 1e-5f);

    float4 Gc = g4 [8 * 256 + tid];
    float4 Bc = bt4[8 * 256 + tid];
    const float* gc = (const float*)&Gc;
    const float* bc = (const float*)&Bc;

    float4 hn4, cn4;
    float* hn = (float*)&hn4;  float* cn = (float*)&cn4;
#pragma unroll
    for (int jj = 0; jj < 4; jj++) {
        float lnc = gc[jj] * (cvals[jj] - cmu) * crs + bc[jj];
        hn[jj] = sigmoid_ap(ovals[jj]) * tanh_ap(lnc);
        cn[jj] = cvals[jj];
    }
    float4* out4 = (float4*)out;
    out4[(size_t)b * 256 + tid] = hn4;
    out4[(size_t)BATCH * 256 + (size_t)b * 256 + tid] = cn4;
}

// ---------------------------------------------------------------------------
// kernel_launch
// ---------------------------------------------------------------------------
extern "C" void kernel_launch(void* const* d_in, const int* in_sizes, int n_in,
                              void* d_out, int out_size)
{
    const float* x   = (const float*)d_in[0];
    const float* h   = (const float*)d_in[1];
    const float* c   = (const float*)d_in[2];
    const float* wih = (const float*)d_in[3];
    const float* whh = (const float*)d_in[4];
    const float* bih = (const float*)d_in[5];
    const float* gma = (const float*)d_in[6];
    const float* bta = (const float*)d_in[7];
    float* out = (float*)d_out;

    dim3 cgrid(BATCH * KDIM / 16 / 256, 4);
    cvt_kernel<<<cgrid, 256>>>((const float4*)x, (const float4*)h,
                               (const float4*)wih, (const float4*)whh);

    cudaFuncSetAttribute(gemm_f16, cudaFuncAttributeMaxDynamicSharedMemorySize, SMEM_TOTAL);
    dim3 ggrid(NDIM / BN, BATCH / BM, 2);
    gemm_f16<<<ggrid, 256, SMEM_TOTAL>>>();

    ln_cell_kernel<<<BATCH, 256>>>(c, bih, gma, bta, out);
}